// round 1
// baseline (speedup 1.0000x reference)
#include <cuda_runtime.h>
#include <math.h>

#define Bb 8
#define Ss 512
#define Hh 1024
#define Ee 8
#define NHEAD 8
#define HD 64
#define HSUB 512
#define INTER 1536
#define NPAIR 16
#define QKVW 1536
#define GUW 3072

// ---------------- scratch (device globals; no allocs allowed) ----------------
__device__ float g_h[Bb * Ss * Hh];           // hidden + injection   (16MB)
__device__ float g_hs[NPAIR * Ss * HSUB];     // hs0 -> hs1 -> hs2    (16MB)
__device__ float g_qkv[NPAIR * Ss * QKVW];    // qkv, later act       (48MB)
__device__ float g_att[NPAIR * Ss * HSUB];    // attention out        (16MB)
__device__ float g_tmp[NPAIR * Ss * HSUB];    // pre-residual gemm out(16MB)
__device__ float g_gu[NPAIR * Ss * GUW];      // gate_up out          (96MB)
__device__ float g_up[NPAIR * Ss * Hh];       // per-pair final out   (32MB)
__device__ int   g_pair_e[NPAIR];
__device__ float g_pair_w[NPAIR];

// ---------------- elementwise: h = hidden + injection ----------------
__global__ void add_kernel(const float* __restrict__ a, const float* __restrict__ b) {
    int i = blockIdx.x * 256 + threadIdx.x;   // over float4 count
    float4 va = ((const float4*)a)[i];
    float4 vb = ((const float4*)b)[i];
    float4 o;
    o.x = va.x + vb.x; o.y = va.y + vb.y; o.z = va.z + vb.z; o.w = va.w + vb.w;
    ((float4*)g_h)[i] = o;
}

// ---------------- routing: logits, softmax, top-2, aux loss ----------------
__global__ void routing_kernel(const float* __restrict__ gate_w, float* __restrict__ aux_out) {
    __shared__ float logits[Bb][Ee];
    __shared__ float probs[Bb][Ee];
    int tid = threadIdx.x;
    if (tid < Bb * Ee) {
        int b = tid >> 3, e = tid & 7;
        const float* hv = g_h + (long)b * Ss * Hh;  // token 0 of batch b
        const float* w = gate_w + e * Hh;
        float acc = 0.f;
        for (int i = 0; i < Hh; i++) acc += hv[i] * w[i];
        logits[b][e] = acc;
    }
    __syncthreads();
    if (tid < Bb) {
        int b = tid;
        float mx = -1e30f;
        for (int e = 0; e < Ee; e++) mx = fmaxf(mx, logits[b][e]);
        float p[Ee]; float sum = 0.f;
        for (int e = 0; e < Ee; e++) { p[e] = expf(logits[b][e] - mx); sum += p[e]; }
        for (int e = 0; e < Ee; e++) { p[e] /= sum; probs[b][e] = p[e]; }
        int i1 = 0;
        for (int e = 1; e < Ee; e++) if (p[e] > p[i1]) i1 = e;
        int i2 = -1; float v2 = -1e30f;
        for (int e = 0; e < Ee; e++) if (e != i1 && p[e] > v2) { v2 = p[e]; i2 = e; }
        float denom = fmaxf(p[i1] + v2, 1e-8f);
        g_pair_e[2 * b]     = i1; g_pair_w[2 * b]     = p[i1] / denom;
        g_pair_e[2 * b + 1] = i2; g_pair_w[2 * b + 1] = v2 / denom;
    }
    __syncthreads();
    if (tid == 0) {
        float aux = 0.f;
        for (int e = 0; e < Ee; e++) {
            float imp = 0.f;
            for (int b = 0; b < Bb; b++) imp += probs[b][e];
            imp /= (float)Bb;
            int cnt = 0;
            for (int p = 0; p < NPAIR; p++) if (g_pair_e[p] == e) cnt++;
            float loadf = (float)cnt / (float)(Bb * 2);
            aux += (float)Ee * imp * loadf;
        }
        *aux_out = aux;
    }
}

// ---------------- tiled NT GEMM: C[pair] = A[pair] @ W[expert]^T ----------------
// A (M,K) row-major, W (N,K) row-major, C (M,N) row-major. M=512 always.
// BM=BN=128, BK=16, 256 threads, 8x8 microtile.
__global__ void __launch_bounds__(256)
gemm_nt(const float* __restrict__ Abase, long aStride, int aDiv,
        const float* __restrict__ Wbase, long wStride,
        float* __restrict__ Cbase, long cStride, int K, int N) {
    const int pair = blockIdx.z;
    const float* A = Abase + (long)(pair / aDiv) * aStride;
    const float* W = Wbase + (long)g_pair_e[pair] * wStride;
    float* C = Cbase + (long)pair * cStride;

    __shared__ float As[16][128];
    __shared__ float Bs[16][128];

    int tid = threadIdx.x;
    int tx = tid & 15;   // n micro index
    int ty = tid >> 4;   // m micro index
    int m0 = blockIdx.y * 128;
    int n0 = blockIdx.x * 128;

    float acc[8][8];
#pragma unroll
    for (int i = 0; i < 8; i++)
#pragma unroll
        for (int j = 0; j < 8; j++) acc[i][j] = 0.f;

    for (int k0 = 0; k0 < K; k0 += 16) {
#pragma unroll
        for (int i = 0; i < 2; i++) {
            int lin = tid + i * 256;         // 0..511 float4 slots
            int row = lin >> 2;
            int c4 = (lin & 3) * 4;
            float4 va = *(const float4*)(A + (long)(m0 + row) * K + k0 + c4);
            As[c4 + 0][row] = va.x; As[c4 + 1][row] = va.y;
            As[c4 + 2][row] = va.z; As[c4 + 3][row] = va.w;
            float4 vb = *(const float4*)(W + (long)(n0 + row) * K + k0 + c4);
            Bs[c4 + 0][row] = vb.x; Bs[c4 + 1][row] = vb.y;
            Bs[c4 + 2][row] = vb.z; Bs[c4 + 3][row] = vb.w;
        }
        __syncthreads();
#pragma unroll
        for (int kk = 0; kk < 16; kk++) {
            float a[8], b[8];
            *(float4*)(a)     = *(const float4*)&As[kk][ty * 8];
            *(float4*)(a + 4) = *(const float4*)&As[kk][ty * 8 + 4];
            *(float4*)(b)     = *(const float4*)&Bs[kk][tx * 8];
            *(float4*)(b + 4) = *(const float4*)&Bs[kk][tx * 8 + 4];
#pragma unroll
            for (int i = 0; i < 8; i++)
#pragma unroll
                for (int j = 0; j < 8; j++) acc[i][j] += a[i] * b[j];
        }
        __syncthreads();
    }
#pragma unroll
    for (int i = 0; i < 8; i++) {
        long row = (long)(m0 + ty * 8 + i) * N + n0 + tx * 8;
        float4 o0 = make_float4(acc[i][0], acc[i][1], acc[i][2], acc[i][3]);
        float4 o1 = make_float4(acc[i][4], acc[i][5], acc[i][6], acc[i][7]);
        *(float4*)(C + row) = o0;
        *(float4*)(C + row + 4) = o1;
    }
}

// ---------------- RoPE on q,k heads of g_qkv ----------------
__global__ void rope_kernel(const float* __restrict__ cosb, const float* __restrict__ sinb) {
    int s = blockIdx.x, pair = blockIdx.y;
    int tid = threadIdx.x;               // 512 threads: 16 heads x 32 dims
    int hh = tid >> 5, d = tid & 31;
    float* p = g_qkv + ((long)(pair * Ss + s)) * QKVW + hh * HD;
    float x1 = p[d], x2 = p[d + 32];
    float c1 = cosb[s * HD + d],      s1 = sinb[s * HD + d];
    float c2 = cosb[s * HD + d + 32], s2 = sinb[s * HD + d + 32];
    p[d]      = x1 * c1 - x2 * s1;
    p[d + 32] = x2 * c2 + x1 * s2;
}

// ---------------- flash attention: 32 q-rows per block ----------------
// grid: (16 q-tiles, 8 heads, 16 pairs), 256 threads (8 warps x 4 rows each)
__global__ void __launch_bounds__(256) attn_kernel() {
    __shared__ float qs[32 * 64];       // [qrow][dim]         8KB
    __shared__ float kT[64 * 64];       // [dim][key]         16KB
    __shared__ float vs[64 * 64];       // [key][dim]         16KB
    __shared__ float psm[32 * 64];      // [qrow][key]         8KB  (total 48KB)

    int pair = blockIdx.z, head = blockIdx.y, qt = blockIdx.x;
    const float* base = g_qkv + (long)pair * Ss * QKVW;
    int tid = threadIdx.x;
    int warp = tid >> 5, lane = tid & 31;
    int q0 = qt * 32;

    // load q tile (scaled by 1/sqrt(64))
#pragma unroll
    for (int i = 0; i < 2; i++) {
        int lin = tid + i * 256;          // 512 float4 slots (32 rows x 16)
        int row = lin >> 4;
        int c4 = (lin & 15) * 4;
        float4 v = *(const float4*)(base + (long)(q0 + row) * QKVW + head * HD + c4);
        qs[row * 64 + c4 + 0] = v.x * 0.125f;
        qs[row * 64 + c4 + 1] = v.y * 0.125f;
        qs[row * 64 + c4 + 2] = v.z * 0.125f;
        qs[row * 64 + c4 + 3] = v.w * 0.125f;
    }

    float o[4][2], mrow[4], lrow[4];
#pragma unroll
    for (int r = 0; r < 4; r++) {
        o[r][0] = 0.f; o[r][1] = 0.f; mrow[r] = -1e30f; lrow[r] = 0.f;
    }

    for (int kt = 0; kt < 8; kt++) {
        int k0 = kt * 64;
        __syncthreads();
        // load K (transposed) and V tiles
#pragma unroll
        for (int i = 0; i < 4; i++) {
            int lin = tid + i * 256;       // 1024 float4 slots (64 keys x 16)
            int key = lin >> 4;
            int c4 = (lin & 15) * 4;
            float4 kv = *(const float4*)(base + (long)(k0 + key) * QKVW + 512 + head * HD + c4);
            kT[(c4 + 0) * 64 + key] = kv.x;
            kT[(c4 + 1) * 64 + key] = kv.y;
            kT[(c4 + 2) * 64 + key] = kv.z;
            kT[(c4 + 3) * 64 + key] = kv.w;
            float4 vv = *(const float4*)(base + (long)(k0 + key) * QKVW + 1024 + head * HD + c4);
            vs[key * 64 + c4 + 0] = vv.x;
            vs[key * 64 + c4 + 1] = vv.y;
            vs[key * 64 + c4 + 2] = vv.z;
            vs[key * 64 + c4 + 3] = vv.w;
        }
        __syncthreads();

        // scores: warp handles rows warp*4..+3, lane handles keys {lane, lane+32}
        float sreg[4][2];
#pragma unroll
        for (int r = 0; r < 4; r++) { sreg[r][0] = 0.f; sreg[r][1] = 0.f; }
#pragma unroll 4
        for (int kk = 0; kk < 64; kk++) {
            float kv0 = kT[kk * 64 + lane];
            float kv1 = kT[kk * 64 + lane + 32];
#pragma unroll
            for (int r = 0; r < 4; r++) {
                float qv = qs[(warp * 4 + r) * 64 + kk];
                sreg[r][0] += qv * kv0;
                sreg[r][1] += qv * kv1;
            }
        }

        // online softmax + write p to smem
#pragma unroll
        for (int r = 0; r < 4; r++) {
            float mx = fmaxf(sreg[r][0], sreg[r][1]);
#pragma unroll
            for (int off = 16; off; off >>= 1) mx = fmaxf(mx, __shfl_xor_sync(0xffffffffu, mx, off));
            float mnew = fmaxf(mrow[r], mx);
            float scale = expf(mrow[r] - mnew);
            float p0 = expf(sreg[r][0] - mnew);
            float p1 = expf(sreg[r][1] - mnew);
            float ls = p0 + p1;
#pragma unroll
            for (int off = 16; off; off >>= 1) ls += __shfl_xor_sync(0xffffffffu, ls, off);
            lrow[r] = lrow[r] * scale + ls;
            mrow[r] = mnew;
            o[r][0] *= scale; o[r][1] *= scale;
            psm[(warp * 4 + r) * 64 + lane] = p0;
            psm[(warp * 4 + r) * 64 + lane + 32] = p1;
        }
        __syncwarp();

        // o += p @ v : lane owns dims {lane, lane+32}
#pragma unroll 4
        for (int c = 0; c < 64; c++) {
            float v0 = vs[c * 64 + lane];
            float v1 = vs[c * 64 + lane + 32];
#pragma unroll
            for (int r = 0; r < 4; r++) {
                float pv = psm[(warp * 4 + r) * 64 + c];
                o[r][0] += pv * v0;
                o[r][1] += pv * v1;
            }
        }
        __syncwarp();
    }

#pragma unroll
    for (int r = 0; r < 4; r++) {
        float inv = 1.f / lrow[r];
        long orow = ((long)pair * Ss + q0 + warp * 4 + r) * HSUB + head * HD;
        g_att[orow + lane]      = o[r][0] * inv;
        g_att[orow + lane + 32] = o[r][1] * inv;
    }
}

// ---------------- residual + rmsnorm: g_hs = rmsnorm(g_hs + g_tmp) ----------------
__global__ void resnorm_kernel() {
    long row = blockIdx.x;               // 0 .. NPAIR*Ss-1
    float* a = g_hs + row * HSUB;
    const float* t = g_tmp + row * HSUB;
    int tid = threadIdx.x;               // 256
    float v0 = a[tid] + t[tid];
    float v1 = a[tid + 256] + t[tid + 256];
    float ss = v0 * v0 + v1 * v1;
#pragma unroll
    for (int off = 16; off; off >>= 1) ss += __shfl_xor_sync(0xffffffffu, ss, off);
    __shared__ float red[8];
    __shared__ float stot;
    if ((tid & 31) == 0) red[tid >> 5] = ss;
    __syncthreads();
    if (tid == 0) {
        float tsum = 0.f;
        for (int i = 0; i < 8; i++) tsum += red[i];
        stot = tsum;
    }
    __syncthreads();
    float scale = rsqrtf(stot * (1.f / HSUB) + 1e-5f);
    a[tid] = v0 * scale;
    a[tid + 256] = v1 * scale;
}

// ---------------- silu(gate)*up into g_qkv (reused as act buffer) ----------------
__global__ void silu_kernel() {
    long idx = (long)blockIdx.x * 256 + threadIdx.x;   // NPAIR*Ss*INTER
    long row = idx / INTER;
    int c = (int)(idx - row * INTER);
    const float* gr = g_gu + row * GUW;
    float g = gr[c];
    float u = gr[c + INTER];
    float sg = 1.f / (1.f + expf(-g));
    g_qkv[row * INTER + c] = g * sg * u;
}

// ---------------- final: out = rmsnorm(h + w0*u0 + w1*u1) ----------------
__global__ void final_kernel(float* __restrict__ out) {
    int b = blockIdx.y, s = blockIdx.x;
    float w0 = g_pair_w[2 * b], w1 = g_pair_w[2 * b + 1];
    long r = (long)b * Ss + s;
    const float* hp = g_h + r * Hh;
    const float* u0 = g_up + ((long)(2 * b) * Ss + s) * Hh;
    const float* u1 = g_up + ((long)(2 * b + 1) * Ss + s) * Hh;
    int tid = threadIdx.x;               // 256, 4 elems each
    int c = tid * 4;
    float4 vh = *(const float4*)(hp + c);
    float4 v0 = *(const float4*)(u0 + c);
    float4 v1 = *(const float4*)(u1 + c);
    float y[4];
    y[0] = vh.x + w0 * v0.x + w1 * v1.x;
    y[1] = vh.y + w0 * v0.y + w1 * v1.y;
    y[2] = vh.z + w0 * v0.z + w1 * v1.z;
    y[3] = vh.w + w0 * v0.w + w1 * v1.w;
    float ss = y[0] * y[0] + y[1] * y[1] + y[2] * y[2] + y[3] * y[3];
#pragma unroll
    for (int off = 16; off; off >>= 1) ss += __shfl_xor_sync(0xffffffffu, ss, off);
    __shared__ float red[8];
    __shared__ float stot;
    if ((tid & 31) == 0) red[tid >> 5] = ss;
    __syncthreads();
    if (tid == 0) {
        float tsum = 0.f;
        for (int i = 0; i < 8; i++) tsum += red[i];
        stot = tsum;
    }
    __syncthreads();
    float scale = rsqrtf(stot * (1.f / Hh) + 1e-5f);
    float4 o;
    o.x = y[0] * scale; o.y = y[1] * scale; o.z = y[2] * scale; o.w = y[3] * scale;
    *(float4*)(out + r * Hh + c) = o;
}

// ---------------- launch ----------------
extern "C" void kernel_launch(void* const* d_in, const int* in_sizes, int n_in,
                              void* d_out, int out_size) {
    const float* hidden     = (const float*)d_in[0];
    const float* inj        = (const float*)d_in[1];
    const float* cosb       = (const float*)d_in[2];
    const float* sinb       = (const float*)d_in[3];
    const float* gate_w     = (const float*)d_in[4];
    const float* down_w     = (const float*)d_in[5];
    const float* up_w       = (const float*)d_in[6];
    const float* qkv_w      = (const float*)d_in[7];
    const float* o_w        = (const float*)d_in[8];
    const float* gate_up_w  = (const float*)d_in[9];
    const float* mlp_down_w = (const float*)d_in[10];
    float* out = (float*)d_out;

    void* vp;
    cudaGetSymbolAddress(&vp, g_h);   float* p_h   = (float*)vp;
    cudaGetSymbolAddress(&vp, g_hs);  float* p_hs  = (float*)vp;
    cudaGetSymbolAddress(&vp, g_qkv); float* p_qkv = (float*)vp;
    cudaGetSymbolAddress(&vp, g_att); float* p_att = (float*)vp;
    cudaGetSymbolAddress(&vp, g_tmp); float* p_tmp = (float*)vp;
    cudaGetSymbolAddress(&vp, g_gu);  float* p_gu  = (float*)vp;
    cudaGetSymbolAddress(&vp, g_up);  float* p_up  = (float*)vp;

    // 1. h = hidden + injection
    int n4 = Bb * Ss * Hh / 4;
    add_kernel<<<n4 / 256, 256>>>(hidden, inj);

    // 2. routing (writes pair table + aux loss)
    routing_kernel<<<1, 64>>>(gate_w, out + (out_size - 1));

    // 3. hs0 = h[b] @ down_w[e]^T     (512x512x1024)
    gemm_nt<<<dim3(HSUB / 128, Ss / 128, NPAIR), 256>>>(
        p_h, (long)Ss * Hh, 2, down_w, (long)HSUB * Hh, p_hs, (long)Ss * HSUB, Hh, HSUB);

    // 4. qkv = hs0 @ qkv_w[e]^T       (512x1536x512)
    gemm_nt<<<dim3(QKVW / 128, Ss / 128, NPAIR), 256>>>(
        p_hs, (long)Ss * HSUB, 1, qkv_w, (long)QKVW * HSUB, p_qkv, (long)Ss * QKVW, HSUB, QKVW);

    // 5. RoPE on q,k
    rope_kernel<<<dim3(Ss, NPAIR), 512>>>(cosb, sinb);

    // 6. attention
    attn_kernel<<<dim3(16, NHEAD, NPAIR), 256>>>();

    // 7. o-proj: tmp = att @ o_w[e]^T  (512x512x512)
    gemm_nt<<<dim3(HSUB / 128, Ss / 128, NPAIR), 256>>>(
        p_att, (long)Ss * HSUB, 1, o_w, (long)HSUB * HSUB, p_tmp, (long)Ss * HSUB, HSUB, HSUB);

    // 8. hs1 = rmsnorm(hs0 + tmp)
    resnorm_kernel<<<NPAIR * Ss, 256>>>();

    // 9. gu = hs1 @ gate_up_w[e]^T    (512x3072x512)
    gemm_nt<<<dim3(GUW / 128, Ss / 128, NPAIR), 256>>>(
        p_hs, (long)Ss * HSUB, 1, gate_up_w, (long)GUW * HSUB, p_gu, (long)Ss * GUW, HSUB, GUW);

    // 10. act = silu(gate)*up  -> g_qkv buffer
    silu_kernel<<<(NPAIR * Ss * INTER) / 256, 256>>>();

    // 11. tmp = act @ mlp_down_w[e]^T (512x512x1536)
    gemm_nt<<<dim3(HSUB / 128, Ss / 128, NPAIR), 256>>>(
        p_qkv, (long)Ss * INTER, 1, mlp_down_w, (long)HSUB * INTER, p_tmp, (long)Ss * HSUB, INTER, HSUB);

    // 12. hs2 = rmsnorm(hs1 + tmp)
    resnorm_kernel<<<NPAIR * Ss, 256>>>();

    // 13. up_out = hs2 @ up_w[e]^T    (512x1024x512)
    gemm_nt<<<dim3(Hh / 128, Ss / 128, NPAIR), 256>>>(
        p_hs, (long)Ss * HSUB, 1, up_w, (long)Hh * HSUB, p_up, (long)Ss * Hh, HSUB, Hh);

    // 14. out = rmsnorm(h + w0*u0 + w1*u1)
    final_kernel<<<dim3(Ss, Bb), 256>>>(out);
}

// round 3
// speedup vs baseline: 1.4488x; 1.4488x over previous
#include <cuda_runtime.h>
#include <cuda_bf16.h>
#include <math.h>
#include <stdint.h>

#define Bb 8
#define Ss 512
#define Hh 1024
#define Ee 8
#define NHEAD 8
#define HD 64
#define HSUB 512
#define INTER 1536
#define NPAIR 16
#define QKVW 1536
#define GUW 3072

// ---------------- scratch (device globals; no allocs allowed) ----------------
__device__ float g_h[Bb * Ss * Hh];
__device__ float g_hs[NPAIR * Ss * HSUB];
__device__ float g_qkv[NPAIR * Ss * QKVW];    // qkv, later act buffer
__device__ float g_att[NPAIR * Ss * HSUB];
__device__ float g_tmp[NPAIR * Ss * HSUB];
__device__ float g_gu[NPAIR * Ss * GUW];
__device__ float g_up[NPAIR * Ss * Hh];
__device__ int   g_pair_e[NPAIR];
__device__ float g_pair_w[NPAIR];

// 3-term bf16 planes folded along K:  A' = [hi|lo|hi], W' = [hi|hi|lo]
// float-element offsets of each weight (x3 for plane elements)
#define OFF_DOWN 0L
#define OFF_QKV  4194304L
#define OFF_O    10485760L
#define OFF_GU   12582912L
#define OFF_MLPD 25165824L
#define OFF_UP   31457280L
#define W_TOTAL  35651584L
__device__ unsigned short g_w3[W_TOTAL * 3];              // 214MB
__device__ unsigned short g_a3[NPAIR * Ss * INTER * 3];   // 75.5MB

// ---------------- elementwise: h = hidden + injection ----------------
__global__ void add_kernel(const float* __restrict__ a, const float* __restrict__ b) {
    int i = blockIdx.x * 256 + threadIdx.x;
    float4 va = ((const float4*)a)[i];
    float4 vb = ((const float4*)b)[i];
    float4 o;
    o.x = va.x + vb.x; o.y = va.y + vb.y; o.z = va.z + vb.z; o.w = va.w + vb.w;
    ((float4*)g_h)[i] = o;
}

// ---------------- fp32 -> folded 3-term bf16 planes ----------------
// modeA=1: [hi | lo | hi]   modeA=0: [hi | hi | lo]
__global__ void cvt3_kernel(const float* __restrict__ src,
                            unsigned short* __restrict__ dst,
                            int K4, int modeA) {
    long i = (long)blockIdx.x * 256 + threadIdx.x;
    long row = i / K4;
    int kc = (int)(i - row * K4);
    float4 v = ((const float4*)src)[i];
    float x[4] = {v.x, v.y, v.z, v.w};
    unsigned int h[4], l[4];
#pragma unroll
    for (int j = 0; j < 4; j++) {
        __nv_bfloat16 hb = __float2bfloat16(x[j]);
        float r = x[j] - __bfloat162float(hb);
        __nv_bfloat16 lb = __float2bfloat16(r);
        h[j] = (unsigned int)__bfloat16_as_ushort(hb);
        l[j] = (unsigned int)__bfloat16_as_ushort(lb);
    }
    uint2 uh, ul;
    uh.x = h[0] | (h[1] << 16); uh.y = h[2] | (h[3] << 16);
    ul.x = l[0] | (l[1] << 16); ul.y = l[2] | (l[3] << 16);
    long K = (long)K4 * 4;
    unsigned short* base = dst + row * 3 * K + (long)kc * 4;
    *(uint2*)base = uh;
    if (modeA) {
        *(uint2*)(base + K)     = ul;
        *(uint2*)(base + 2 * K) = uh;
    } else {
        *(uint2*)(base + K)     = uh;
        *(uint2*)(base + 2 * K) = ul;
    }
}

// ---------------- routing ----------------
__global__ void routing_kernel(const float* __restrict__ gate_w, float* __restrict__ aux_out) {
    __shared__ float logits[Bb][Ee];
    __shared__ float probs[Bb][Ee];
    int tid = threadIdx.x;
    if (tid < Bb * Ee) {
        int b = tid >> 3, e = tid & 7;
        const float* hv = g_h + (long)b * Ss * Hh;
        const float* w = gate_w + e * Hh;
        float acc = 0.f;
        for (int i = 0; i < Hh; i++) acc += hv[i] * w[i];
        logits[b][e] = acc;
    }
    __syncthreads();
    if (tid < Bb) {
        int b = tid;
        float mx = -1e30f;
        for (int e = 0; e < Ee; e++) mx = fmaxf(mx, logits[b][e]);
        float p[Ee]; float sum = 0.f;
        for (int e = 0; e < Ee; e++) { p[e] = expf(logits[b][e] - mx); sum += p[e]; }
        for (int e = 0; e < Ee; e++) { p[e] /= sum; probs[b][e] = p[e]; }
        int i1 = 0;
        for (int e = 1; e < Ee; e++) if (p[e] > p[i1]) i1 = e;
        int i2 = -1; float v2 = -1e30f;
        for (int e = 0; e < Ee; e++) if (e != i1 && p[e] > v2) { v2 = p[e]; i2 = e; }
        float denom = fmaxf(p[i1] + v2, 1e-8f);
        g_pair_e[2 * b]     = i1; g_pair_w[2 * b]     = p[i1] / denom;
        g_pair_e[2 * b + 1] = i2; g_pair_w[2 * b + 1] = v2 / denom;
    }
    __syncthreads();
    if (tid == 0) {
        float aux = 0.f;
        for (int e = 0; e < Ee; e++) {
            float imp = 0.f;
            for (int b = 0; b < Bb; b++) imp += probs[b][e];
            imp /= (float)Bb;
            int cnt = 0;
            for (int p = 0; p < NPAIR; p++) if (g_pair_e[p] == e) cnt++;
            float loadf = (float)cnt / (float)(Bb * 2);
            aux += (float)Ee * imp * loadf;
        }
        *aux_out = aux;
    }
}

// ---------------- mma.sync bf16 GEMM: C[pair] = A'[pair] @ W'[e]^T ----------------
// A' (512, K3) row-major bf16; W' (N, K3) row-major bf16 per expert; C fp32 (512, N).
// Tile 128x128, BK=32, 8 warps (2m x 4n), warp tile 64x32, double-buffered.
#define SROW 40   // smem row stride in bf16 elems (80B, pads 64B rows)

__global__ void __launch_bounds__(256, 2) gemm_mma(
    const unsigned short* __restrict__ A, int aDiv,
    const unsigned short* __restrict__ W,
    float* __restrict__ C, int K3, int N)
{
    __shared__ unsigned short As[2][128 * SROW];
    __shared__ unsigned short Wsm[2][128 * SROW];

    int tid = threadIdx.x;
    int wid = tid >> 5, lane = tid & 31;
    int g = lane >> 2, t2 = (lane & 3) * 2;
    int wm = wid & 1, wn = wid >> 1;             // warp grid 2 x 4
    int pair = blockIdx.z;
    int m0 = blockIdx.y * 128, n0 = blockIdx.x * 128;

    const unsigned short* gA = A + (long)(pair / aDiv) * Ss * K3 + (long)m0 * K3;
    const unsigned short* gW = W + (long)g_pair_e[pair] * N * K3 + (long)n0 * K3;

    float acc[4][4][4];
#pragma unroll
    for (int i = 0; i < 4; i++)
#pragma unroll
        for (int j = 0; j < 4; j++)
#pragma unroll
            for (int k = 0; k < 4; k++) acc[i][j][k] = 0.f;

    // stage slots: thread covers slots {tid, tid+256}; slot s: row=s>>2, chunk=s&3 (8 bf16)
    int r0 = tid >> 2, kc = (tid & 3) * 8;
    int r1 = r0 + 64;
    int sA0 = r0 * SROW + kc, sA1 = r1 * SROW + kc;

    // prologue: tile 0
    {
        *(uint4*)&As [0][sA0] = *(const uint4*)(gA + (long)r0 * K3 + kc);
        *(uint4*)&As [0][sA1] = *(const uint4*)(gA + (long)r1 * K3 + kc);
        *(uint4*)&Wsm[0][sA0] = *(const uint4*)(gW + (long)r0 * K3 + kc);
        *(uint4*)&Wsm[0][sA1] = *(const uint4*)(gW + (long)r1 * K3 + kc);
    }
    __syncthreads();

    int nc = K3 >> 5;
    uint4 pa0, pa1, pw0, pw1;
    for (int c = 0; c < nc; c++) {
        int p = c & 1;
        if (c + 1 < nc) {
            long kb = (long)(c + 1) * 32 + kc;
            pa0 = *(const uint4*)(gA + (long)r0 * K3 + kb);
            pa1 = *(const uint4*)(gA + (long)r1 * K3 + kb);
            pw0 = *(const uint4*)(gW + (long)r0 * K3 + kb);
            pw1 = *(const uint4*)(gW + (long)r1 * K3 + kb);
        }
#pragma unroll
        for (int kk = 0; kk < 2; kk++) {
            unsigned af[4][4], bf[4][2];
#pragma unroll
            for (int mt = 0; mt < 4; mt++) {
                int base = (wm * 64 + mt * 16 + g) * SROW + kk * 16 + t2;
                af[mt][0] = *(const unsigned*)&As[p][base];
                af[mt][1] = *(const unsigned*)&As[p][base + 8 * SROW];
                af[mt][2] = *(const unsigned*)&As[p][base + 8];
                af[mt][3] = *(const unsigned*)&As[p][base + 8 * SROW + 8];
            }
#pragma unroll
            for (int nt = 0; nt < 4; nt++) {
                int base = (wn * 32 + nt * 8 + g) * SROW + kk * 16 + t2;
                bf[nt][0] = *(const unsigned*)&Wsm[p][base];
                bf[nt][1] = *(const unsigned*)&Wsm[p][base + 8];
            }
#pragma unroll
            for (int mt = 0; mt < 4; mt++)
#pragma unroll
                for (int nt = 0; nt < 4; nt++) {
                    asm volatile(
                        "mma.sync.aligned.m16n8k16.row.col.f32.bf16.bf16.f32 "
                        "{%0,%1,%2,%3}, {%4,%5,%6,%7}, {%8,%9}, {%0,%1,%2,%3};"
                        : "+f"(acc[mt][nt][0]), "+f"(acc[mt][nt][1]),
                          "+f"(acc[mt][nt][2]), "+f"(acc[mt][nt][3])
                        : "r"(af[mt][0]), "r"(af[mt][1]), "r"(af[mt][2]), "r"(af[mt][3]),
                          "r"(bf[nt][0]), "r"(bf[nt][1]));
                }
        }
        if (c + 1 < nc) {
            *(uint4*)&As [p ^ 1][sA0] = pa0;
            *(uint4*)&As [p ^ 1][sA1] = pa1;
            *(uint4*)&Wsm[p ^ 1][sA0] = pw0;
            *(uint4*)&Wsm[p ^ 1][sA1] = pw1;
        }
        __syncthreads();
    }

    // epilogue
    float* Cp = C + (long)pair * Ss * N;
#pragma unroll
    for (int mt = 0; mt < 4; mt++) {
        int m = m0 + wm * 64 + mt * 16 + g;
#pragma unroll
        for (int nt = 0; nt < 4; nt++) {
            int n = n0 + wn * 32 + nt * 8 + t2;
            float2 v0 = make_float2(acc[mt][nt][0], acc[mt][nt][1]);
            float2 v1 = make_float2(acc[mt][nt][2], acc[mt][nt][3]);
            *(float2*)(Cp + (long)m * N + n) = v0;
            *(float2*)(Cp + (long)(m + 8) * N + n) = v1;
        }
    }
}

// ---------------- RoPE on q,k heads of g_qkv ----------------
__global__ void rope_kernel(const float* __restrict__ cosb, const float* __restrict__ sinb) {
    int s = blockIdx.x, pair = blockIdx.y;
    int tid = threadIdx.x;               // 512 threads: 16 heads x 32 dims
    int hh = tid >> 5, d = tid & 31;
    float* p = g_qkv + ((long)(pair * Ss + s)) * QKVW + hh * HD;
    float x1 = p[d], x2 = p[d + 32];
    float c1 = cosb[s * HD + d],      s1 = sinb[s * HD + d];
    float c2 = cosb[s * HD + d + 32], s2 = sinb[s * HD + d + 32];
    p[d]      = x1 * c1 - x2 * s1;
    p[d + 32] = x2 * c2 + x1 * s2;
}

// ---------------- flash attention ----------------
__global__ void __launch_bounds__(256) attn_kernel() {
    __shared__ float qs[32 * 64];
    __shared__ float kT[64 * 64];
    __shared__ float vs[64 * 64];
    __shared__ float psm[32 * 64];

    int pair = blockIdx.z, head = blockIdx.y, qt = blockIdx.x;
    const float* base = g_qkv + (long)pair * Ss * QKVW;
    int tid = threadIdx.x;
    int warp = tid >> 5, lane = tid & 31;
    int q0 = qt * 32;

#pragma unroll
    for (int i = 0; i < 2; i++) {
        int lin = tid + i * 256;
        int row = lin >> 4;
        int c4 = (lin & 15) * 4;
        float4 v = *(const float4*)(base + (long)(q0 + row) * QKVW + head * HD + c4);
        qs[row * 64 + c4 + 0] = v.x * 0.125f;
        qs[row * 64 + c4 + 1] = v.y * 0.125f;
        qs[row * 64 + c4 + 2] = v.z * 0.125f;
        qs[row * 64 + c4 + 3] = v.w * 0.125f;
    }

    float o[4][2], mrow[4], lrow[4];
#pragma unroll
    for (int r = 0; r < 4; r++) {
        o[r][0] = 0.f; o[r][1] = 0.f; mrow[r] = -1e30f; lrow[r] = 0.f;
    }

    for (int kt = 0; kt < 8; kt++) {
        int k0 = kt * 64;
        __syncthreads();
#pragma unroll
        for (int i = 0; i < 4; i++) {
            int lin = tid + i * 256;
            int key = lin >> 4;
            int c4 = (lin & 15) * 4;
            float4 kv = *(const float4*)(base + (long)(k0 + key) * QKVW + 512 + head * HD + c4);
            kT[(c4 + 0) * 64 + key] = kv.x;
            kT[(c4 + 1) * 64 + key] = kv.y;
            kT[(c4 + 2) * 64 + key] = kv.z;
            kT[(c4 + 3) * 64 + key] = kv.w;
            float4 vv = *(const float4*)(base + (long)(k0 + key) * QKVW + 1024 + head * HD + c4);
            vs[key * 64 + c4 + 0] = vv.x;
            vs[key * 64 + c4 + 1] = vv.y;
            vs[key * 64 + c4 + 2] = vv.z;
            vs[key * 64 + c4 + 3] = vv.w;
        }
        __syncthreads();

        float sreg[4][2];
#pragma unroll
        for (int r = 0; r < 4; r++) { sreg[r][0] = 0.f; sreg[r][1] = 0.f; }
#pragma unroll 4
        for (int kk = 0; kk < 64; kk++) {
            float kv0 = kT[kk * 64 + lane];
            float kv1 = kT[kk * 64 + lane + 32];
#pragma unroll
            for (int r = 0; r < 4; r++) {
                float qv = qs[(warp * 4 + r) * 64 + kk];
                sreg[r][0] += qv * kv0;
                sreg[r][1] += qv * kv1;
            }
        }

#pragma unroll
        for (int r = 0; r < 4; r++) {
            float mx = fmaxf(sreg[r][0], sreg[r][1]);
#pragma unroll
            for (int off = 16; off; off >>= 1) mx = fmaxf(mx, __shfl_xor_sync(0xffffffffu, mx, off));
            float mnew = fmaxf(mrow[r], mx);
            float scale = expf(mrow[r] - mnew);
            float p0 = expf(sreg[r][0] - mnew);
            float p1 = expf(sreg[r][1] - mnew);
            float ls = p0 + p1;
#pragma unroll
            for (int off = 16; off; off >>= 1) ls += __shfl_xor_sync(0xffffffffu, ls, off);
            lrow[r] = lrow[r] * scale + ls;
            mrow[r] = mnew;
            o[r][0] *= scale; o[r][1] *= scale;
            psm[(warp * 4 + r) * 64 + lane] = p0;
            psm[(warp * 4 + r) * 64 + lane + 32] = p1;
        }
        __syncwarp();

#pragma unroll 4
        for (int c = 0; c < 64; c++) {
            float v0 = vs[c * 64 + lane];
            float v1 = vs[c * 64 + lane + 32];
#pragma unroll
            for (int r = 0; r < 4; r++) {
                float pv = psm[(warp * 4 + r) * 64 + c];
                o[r][0] += pv * v0;
                o[r][1] += pv * v1;
            }
        }
        __syncwarp();
    }

#pragma unroll
    for (int r = 0; r < 4; r++) {
        float inv = 1.f / lrow[r];
        long orow = ((long)pair * Ss + q0 + warp * 4 + r) * HSUB + head * HD;
        g_att[orow + lane]      = o[r][0] * inv;
        g_att[orow + lane + 32] = o[r][1] * inv;
    }
}

// ---------------- residual + rmsnorm ----------------
__global__ void resnorm_kernel() {
    long row = blockIdx.x;
    float* a = g_hs + row * HSUB;
    const float* t = g_tmp + row * HSUB;
    int tid = threadIdx.x;
    float v0 = a[tid] + t[tid];
    float v1 = a[tid + 256] + t[tid + 256];
    float ss = v0 * v0 + v1 * v1;
#pragma unroll
    for (int off = 16; off; off >>= 1) ss += __shfl_xor_sync(0xffffffffu, ss, off);
    __shared__ float red[8];
    __shared__ float stot;
    if ((tid & 31) == 0) red[tid >> 5] = ss;
    __syncthreads();
    if (tid == 0) {
        float tsum = 0.f;
        for (int i = 0; i < 8; i++) tsum += red[i];
        stot = tsum;
    }
    __syncthreads();
    float scale = rsqrtf(stot * (1.f / HSUB) + 1e-5f);
    a[tid] = v0 * scale;
    a[tid + 256] = v1 * scale;
}

// ---------------- silu(gate)*up ----------------
__global__ void silu_kernel() {
    long idx = (long)blockIdx.x * 256 + threadIdx.x;
    long row = idx / INTER;
    int c = (int)(idx - row * INTER);
    const float* gr = g_gu + row * GUW;
    float g = gr[c];
    float u = gr[c + INTER];
    float sg = 1.f / (1.f + expf(-g));
    g_qkv[row * INTER + c] = g * sg * u;
}

// ---------------- final ----------------
__global__ void final_kernel(float* __restrict__ out) {
    int b = blockIdx.y, s = blockIdx.x;
    float w0 = g_pair_w[2 * b], w1 = g_pair_w[2 * b + 1];
    long r = (long)b * Ss + s;
    const float* hp = g_h + r * Hh;
    const float* u0 = g_up + ((long)(2 * b) * Ss + s) * Hh;
    const float* u1 = g_up + ((long)(2 * b + 1) * Ss + s) * Hh;
    int tid = threadIdx.x;
    int c = tid * 4;
    float4 vh = *(const float4*)(hp + c);
    float4 v0 = *(const float4*)(u0 + c);
    float4 v1 = *(const float4*)(u1 + c);
    float y[4];
    y[0] = vh.x + w0 * v0.x + w1 * v1.x;
    y[1] = vh.y + w0 * v0.y + w1 * v1.y;
    y[2] = vh.z + w0 * v0.z + w1 * v1.z;
    y[3] = vh.w + w0 * v0.w + w1 * v1.w;
    float ss = y[0] * y[0] + y[1] * y[1] + y[2] * y[2] + y[3] * y[3];
#pragma unroll
    for (int off = 16; off; off >>= 1) ss += __shfl_xor_sync(0xffffffffu, ss, off);
    __shared__ float red[8];
    __shared__ float stot;
    if ((tid & 31) == 0) red[tid >> 5] = ss;
    __syncthreads();
    if (tid == 0) {
        float tsum = 0.f;
        for (int i = 0; i < 8; i++) tsum += red[i];
        stot = tsum;
    }
    __syncthreads();
    float scale = rsqrtf(stot * (1.f / Hh) + 1e-5f);
    float4 o;
    o.x = y[0] * scale; o.y = y[1] * scale; o.z = y[2] * scale; o.w = y[3] * scale;
    *(float4*)(out + r * Hh + c) = o;
}

// ---------------- launch ----------------
extern "C" void kernel_launch(void* const* d_in, const int* in_sizes, int n_in,
                              void* d_out, int out_size) {
    const float* hidden     = (const float*)d_in[0];
    const float* inj        = (const float*)d_in[1];
    const float* cosb       = (const float*)d_in[2];
    const float* sinb       = (const float*)d_in[3];
    const float* gate_w     = (const float*)d_in[4];
    const float* down_w     = (const float*)d_in[5];
    const float* up_w       = (const float*)d_in[6];
    const float* qkv_w      = (const float*)d_in[7];
    const float* o_w        = (const float*)d_in[8];
    const float* gate_up_w  = (const float*)d_in[9];
    const float* mlp_down_w = (const float*)d_in[10];
    float* out = (float*)d_out;

    void* vp;
    cudaGetSymbolAddress(&vp, g_h);   float* p_h   = (float*)vp;
    cudaGetSymbolAddress(&vp, g_hs);  float* p_hs  = (float*)vp;
    cudaGetSymbolAddress(&vp, g_qkv); float* p_qkv = (float*)vp;
    cudaGetSymbolAddress(&vp, g_att); float* p_att = (float*)vp;
    cudaGetSymbolAddress(&vp, g_tmp); float* p_tmp = (float*)vp;
    cudaGetSymbolAddress(&vp, g_gu);  float* p_gu  = (float*)vp;
    cudaGetSymbolAddress(&vp, g_up);  float* p_up  = (float*)vp;
    cudaGetSymbolAddress(&vp, g_w3);  unsigned short* p_w3 = (unsigned short*)vp;
    cudaGetSymbolAddress(&vp, g_a3);  unsigned short* p_a3 = (unsigned short*)vp;

    // weight plane folding (hi/lo 3-term, W-mode)
    cvt3_kernel<<<(int)(4194304L / 4 / 256), 256>>>(down_w,     p_w3 + 3 * OFF_DOWN, 1024 / 4, 0);
    cvt3_kernel<<<(int)(6291456L / 4 / 256), 256>>>(qkv_w,      p_w3 + 3 * OFF_QKV,  512 / 4,  0);
    cvt3_kernel<<<(int)(2097152L / 4 / 256), 256>>>(o_w,        p_w3 + 3 * OFF_O,    512 / 4,  0);
    cvt3_kernel<<<(int)(12582912L / 4 / 256), 256>>>(gate_up_w, p_w3 + 3 * OFF_GU,   512 / 4,  0);
    cvt3_kernel<<<(int)(6291456L / 4 / 256), 256>>>(mlp_down_w, p_w3 + 3 * OFF_MLPD, 1536 / 4, 0);
    cvt3_kernel<<<(int)(4194304L / 4 / 256), 256>>>(up_w,       p_w3 + 3 * OFF_UP,   512 / 4,  0);

    // 1. h = hidden + injection ; routing
    int n4 = Bb * Ss * Hh / 4;
    add_kernel<<<n4 / 256, 256>>>(hidden, inj);
    routing_kernel<<<1, 64>>>(gate_w, out + (out_size - 1));

    // 2. hs0 = h @ down_w^T  (K=1024, N=512)
    cvt3_kernel<<<(Bb * Ss * Hh / 4) / 256, 256>>>(p_h, p_a3, 1024 / 4, 1);
    gemm_mma<<<dim3(HSUB / 128, 4, NPAIR), 256>>>(p_a3, 2, p_w3 + 3 * OFF_DOWN, p_hs, 3 * Hh, HSUB);

    // 3. qkv = hs0 @ qkv_w^T  (K=512, N=1536)
    cvt3_kernel<<<(NPAIR * Ss * HSUB / 4) / 256, 256>>>(p_hs, p_a3, 512 / 4, 1);
    gemm_mma<<<dim3(QKVW / 128, 4, NPAIR), 256>>>(p_a3, 1, p_w3 + 3 * OFF_QKV, p_qkv, 3 * HSUB, QKVW);

    // 4. rope + attention
    rope_kernel<<<dim3(Ss, NPAIR), 512>>>(cosb, sinb);
    attn_kernel<<<dim3(16, NHEAD, NPAIR), 256>>>();

    // 5. tmp = att @ o_w^T  (K=512, N=512)
    cvt3_kernel<<<(NPAIR * Ss * HSUB / 4) / 256, 256>>>(p_att, p_a3, 512 / 4, 1);
    gemm_mma<<<dim3(HSUB / 128, 4, NPAIR), 256>>>(p_a3, 1, p_w3 + 3 * OFF_O, p_tmp, 3 * HSUB, HSUB);

    // 6. hs1 = rmsnorm(hs0 + tmp)
    resnorm_kernel<<<NPAIR * Ss, 256>>>();

    // 7. gu = hs1 @ gate_up_w^T  (K=512, N=3072)
    cvt3_kernel<<<(NPAIR * Ss * HSUB / 4) / 256, 256>>>(p_hs, p_a3, 512 / 4, 1);
    gemm_mma<<<dim3(GUW / 128, 4, NPAIR), 256>>>(p_a3, 1, p_w3 + 3 * OFF_GU, p_gu, 3 * HSUB, GUW);

    // 8. act = silu(gate)*up
    silu_kernel<<<(NPAIR * Ss * INTER) / 256, 256>>>();

    // 9. tmp = act @ mlp_down_w^T  (K=1536, N=512)
    cvt3_kernel<<<(NPAIR * Ss * INTER / 4) / 256, 256>>>(p_qkv, p_a3, 1536 / 4, 1);
    gemm_mma<<<dim3(HSUB / 128, 4, NPAIR), 256>>>(p_a3, 1, p_w3 + 3 * OFF_MLPD, p_tmp, 3 * INTER, HSUB);

    // 10. hs2 = rmsnorm(hs1 + tmp)
    resnorm_kernel<<<NPAIR * Ss, 256>>>();

    // 11. up_out = hs2 @ up_w^T  (K=512, N=1024)
    cvt3_kernel<<<(NPAIR * Ss * HSUB / 4) / 256, 256>>>(p_hs, p_a3, 512 / 4, 1);
    gemm_mma<<<dim3(Hh / 128, 4, NPAIR), 256>>>(p_a3, 1, p_w3 + 3 * OFF_UP, p_up, 3 * HSUB, Hh);

    // 12. out = rmsnorm(h + w0*u0 + w1*u1)
    final_kernel<<<dim3(Ss, Bb), 256>>>(out);
}

// round 4
// speedup vs baseline: 1.9981x; 1.3792x over previous
#include <cuda_runtime.h>
#include <cuda_bf16.h>
#include <math.h>
#include <stdint.h>

#define Bb 8
#define Ss 512
#define Hh 1024
#define Ee 8
#define NHEAD 8
#define HD 64
#define HSUB 512
#define INTER 1536
#define NPAIR 16
#define QKVW 1536
#define GUW 3072

// ---------------- scratch (device globals; no allocs allowed) ----------------
__device__ float g_h[Bb * Ss * Hh];
__device__ float g_hs[NPAIR * Ss * HSUB];
__device__ float g_qkv[NPAIR * Ss * QKVW];
__device__ float g_att[NPAIR * Ss * HSUB];
__device__ float g_tmp[NPAIR * Ss * HSUB];
__device__ float g_gu[NPAIR * Ss * GUW];
__device__ float g_up[NPAIR * Ss * Hh];
__device__ int   g_pair_e[NPAIR];
__device__ float g_pair_w[NPAIR];

// 3-term bf16 planes folded along K:  A' = [hi|lo|hi], W' = [hi|hi|lo]
#define OFF_DOWN 0L
#define OFF_QKV  4194304L
#define OFF_O    10485760L
#define OFF_GU   12582912L
#define OFF_MLPD 25165824L
#define OFF_UP   31457280L
#define W_TOTAL  35651584L
__device__ unsigned short g_w3[W_TOTAL * 3];
__device__ unsigned short g_a3[NPAIR * Ss * INTER * 3];

// ---------------- PTX helpers ----------------
__device__ __forceinline__ uint32_t smem_u32(const void* p) {
    uint32_t a;
    asm("{ .reg .u64 t; cvta.to.shared.u64 t, %1; cvt.u32.u64 %0, t; }" : "=r"(a) : "l"(p));
    return a;
}
#define CP_ASYNC(sm, gp) asm volatile("cp.async.cg.shared.global [%0], [%1], 16;" :: "r"(sm), "l"(gp))
#define CP_COMMIT()      asm volatile("cp.async.commit_group;" ::: "memory")
#define CP_WAIT1()       asm volatile("cp.async.wait_group 1;" ::: "memory")
#define LDMX4(r0, r1, r2, r3, a) \
    asm volatile("ldmatrix.sync.aligned.m8n8.x4.shared.b16 {%0,%1,%2,%3}, [%4];" \
        : "=r"(r0), "=r"(r1), "=r"(r2), "=r"(r3) : "r"(a))

// ---------------- elementwise: h = hidden + injection ----------------
__global__ void add_kernel(const float* __restrict__ a, const float* __restrict__ b) {
    int i = blockIdx.x * 256 + threadIdx.x;
    float4 va = ((const float4*)a)[i];
    float4 vb = ((const float4*)b)[i];
    float4 o;
    o.x = va.x + vb.x; o.y = va.y + vb.y; o.z = va.z + vb.z; o.w = va.w + vb.w;
    ((float4*)g_h)[i] = o;
}

// ---------------- fp32 -> folded 3-term bf16 planes ----------------
__global__ void cvt3_kernel(const float* __restrict__ src,
                            unsigned short* __restrict__ dst,
                            int K4, int modeA) {
    long i = (long)blockIdx.x * 256 + threadIdx.x;
    long row = i / K4;
    int kc = (int)(i - row * K4);
    float4 v = ((const float4*)src)[i];
    float x[4] = {v.x, v.y, v.z, v.w};
    unsigned int h[4], l[4];
#pragma unroll
    for (int j = 0; j < 4; j++) {
        __nv_bfloat16 hb = __float2bfloat16(x[j]);
        float r = x[j] - __bfloat162float(hb);
        __nv_bfloat16 lb = __float2bfloat16(r);
        h[j] = (unsigned int)__bfloat16_as_ushort(hb);
        l[j] = (unsigned int)__bfloat16_as_ushort(lb);
    }
    uint2 uh, ul;
    uh.x = h[0] | (h[1] << 16); uh.y = h[2] | (h[3] << 16);
    ul.x = l[0] | (l[1] << 16); ul.y = l[2] | (l[3] << 16);
    long K = (long)K4 * 4;
    unsigned short* base = dst + row * 3 * K + (long)kc * 4;
    *(uint2*)base = uh;
    if (modeA) {
        *(uint2*)(base + K)     = ul;
        *(uint2*)(base + 2 * K) = uh;
    } else {
        *(uint2*)(base + K)     = uh;
        *(uint2*)(base + 2 * K) = ul;
    }
}

// ---------------- routing ----------------
__global__ void routing_kernel(const float* __restrict__ gate_w, float* __restrict__ aux_out) {
    __shared__ float logits[Bb][Ee];
    __shared__ float probs[Bb][Ee];
    int tid = threadIdx.x;
    if (tid < Bb * Ee) {
        int b = tid >> 3, e = tid & 7;
        const float* hv = g_h + (long)b * Ss * Hh;
        const float* w = gate_w + e * Hh;
        float acc = 0.f;
        for (int i = 0; i < Hh; i++) acc += hv[i] * w[i];
        logits[b][e] = acc;
    }
    __syncthreads();
    if (tid < Bb) {
        int b = tid;
        float mx = -1e30f;
        for (int e = 0; e < Ee; e++) mx = fmaxf(mx, logits[b][e]);
        float p[Ee]; float sum = 0.f;
        for (int e = 0; e < Ee; e++) { p[e] = expf(logits[b][e] - mx); sum += p[e]; }
        for (int e = 0; e < Ee; e++) { p[e] /= sum; probs[b][e] = p[e]; }
        int i1 = 0;
        for (int e = 1; e < Ee; e++) if (p[e] > p[i1]) i1 = e;
        int i2 = -1; float v2 = -1e30f;
        for (int e = 0; e < Ee; e++) if (e != i1 && p[e] > v2) { v2 = p[e]; i2 = e; }
        float denom = fmaxf(p[i1] + v2, 1e-8f);
        g_pair_e[2 * b]     = i1; g_pair_w[2 * b]     = p[i1] / denom;
        g_pair_e[2 * b + 1] = i2; g_pair_w[2 * b + 1] = v2 / denom;
    }
    __syncthreads();
    if (tid == 0) {
        float aux = 0.f;
        for (int e = 0; e < Ee; e++) {
            float imp = 0.f;
            for (int b = 0; b < Bb; b++) imp += probs[b][e];
            imp /= (float)Bb;
            int cnt = 0;
            for (int p = 0; p < NPAIR; p++) if (g_pair_e[p] == e) cnt++;
            float loadf = (float)cnt / (float)(Bb * 2);
            aux += (float)Ee * imp * loadf;
        }
        *aux_out = aux;
    }
}

// ---------------- mma.sync bf16 GEMM, cp.async + ldmatrix, BK=64, 3-stage ----------------
// A' (512, K3) row-major bf16; W' (N, K3) row-major bf16 per expert; C fp32 (512, N).
// Tile 128x128x64, 8 warps (2m x 4n), warp tile 64x32.
// smem stage: A 128x64 bf16 (128B rows) + B 128x64 = 32KB; 3 stages = 96KB.
#define GSTAGE_B 32768
#define GB_OFF   16384

__global__ void __launch_bounds__(256, 2) gemm_mma(
    const unsigned short* __restrict__ A, int aDiv,
    const unsigned short* __restrict__ W,
    float* __restrict__ C, int K3, int N)
{
    extern __shared__ __align__(1024) char sm[];
    uint32_t sb = smem_u32(sm);

    int tid = threadIdx.x;
    int wid = tid >> 5, lane = tid & 31;
    int wm = wid & 1, wn = wid >> 1;
    int pair = blockIdx.z;
    int m0 = blockIdx.y * 128, n0 = blockIdx.x * 128;

    const unsigned short* gA = A + (long)(pair / aDiv) * Ss * K3 + (long)m0 * K3;
    const unsigned short* gW = W + (long)g_pair_e[pair] * N * K3 + (long)n0 * K3;

    // ---- cp.async staging geometry: thread t covers rows {t/8 + 32j}, 16B chunk t&7 ----
    int ldRow = tid >> 3, ldC = tid & 7;
    uint32_t soff[4];
    const unsigned short* gAp[4];
    const unsigned short* gWp[4];
#pragma unroll
    for (int j = 0; j < 4; j++) {
        int row = ldRow + 32 * j;
        soff[j] = row * 128 + ((ldC ^ (row & 7)) << 4);
        gAp[j] = gA + (long)row * K3 + ldC * 8;
        gWp[j] = gW + (long)row * K3 + ldC * 8;
    }

    // ---- ldmatrix lane addressing ----
    int l8 = lane & 7;
    int rowA = l8 + 8 * ((lane >> 3) & 1);     // + mt*16 + wm*64
    int cA = lane >> 4;                         // chunk add
    int rowB = l8 + 8 * (lane >> 4);            // + ntp*16 + wn*32
    int cB = (lane >> 3) & 1;
    uint32_t aRowOff = (uint32_t)(wm * 64 + rowA) * 128;
    uint32_t bRowOff = (uint32_t)(wn * 32 + rowB) * 128 + GB_OFF;

    float acc[4][4][4];
#pragma unroll
    for (int i = 0; i < 4; i++)
#pragma unroll
        for (int j = 0; j < 4; j++)
#pragma unroll
            for (int k = 0; k < 4; k++) acc[i][j][k] = 0.f;

    int nc = K3 >> 6;

    // prologue: stages 0 and 1
#pragma unroll
    for (int s = 0; s < 2; s++) {
        uint32_t st = sb + s * GSTAGE_B;
        long kb = (long)s * 64;
#pragma unroll
        for (int j = 0; j < 4; j++) {
            CP_ASYNC(st + soff[j], gAp[j] + kb);
            CP_ASYNC(st + GB_OFF + soff[j], gWp[j] + kb);
        }
        CP_COMMIT();
    }

    int sIdx = 0;   // stage of chunk c
    for (int c = 0; c < nc; c++) {
        CP_WAIT1();
        __syncthreads();
        // issue chunk c+2 into stage (c+2)%3
        if (c + 2 < nc) {
            int s2 = sIdx + 2; if (s2 >= 3) s2 -= 3;
            uint32_t st = sb + s2 * GSTAGE_B;
            long kb = (long)(c + 2) * 64;
#pragma unroll
            for (int j = 0; j < 4; j++) {
                CP_ASYNC(st + soff[j], gAp[j] + kb);
                CP_ASYNC(st + GB_OFF + soff[j], gWp[j] + kb);
            }
            CP_COMMIT();
        } else {
            CP_COMMIT();   // keep group count in sync for wait_group 1
        }

        uint32_t stA = sb + sIdx * GSTAGE_B + aRowOff;
        uint32_t stB = sb + sIdx * GSTAGE_B + bRowOff;
#pragma unroll
        for (int kk = 0; kk < 4; kk++) {
            unsigned af[4][4], bf[4][2];
            uint32_t kxA = (uint32_t)(((2 * kk + cA) ^ l8) << 4);
            uint32_t kxB = (uint32_t)(((2 * kk + cB) ^ l8) << 4);
#pragma unroll
            for (int mt = 0; mt < 4; mt++)
                LDMX4(af[mt][0], af[mt][1], af[mt][2], af[mt][3], stA + mt * 2048 + kxA);
            LDMX4(bf[0][0], bf[0][1], bf[1][0], bf[1][1], stB + kxB);
            LDMX4(bf[2][0], bf[2][1], bf[3][0], bf[3][1], stB + 2048 + kxB);
#pragma unroll
            for (int mt = 0; mt < 4; mt++)
#pragma unroll
                for (int nt = 0; nt < 4; nt++) {
                    asm volatile(
                        "mma.sync.aligned.m16n8k16.row.col.f32.bf16.bf16.f32 "
                        "{%0,%1,%2,%3}, {%4,%5,%6,%7}, {%8,%9}, {%0,%1,%2,%3};"
                        : "+f"(acc[mt][nt][0]), "+f"(acc[mt][nt][1]),
                          "+f"(acc[mt][nt][2]), "+f"(acc[mt][nt][3])
                        : "r"(af[mt][0]), "r"(af[mt][1]), "r"(af[mt][2]), "r"(af[mt][3]),
                          "r"(bf[nt][0]), "r"(bf[nt][1]));
                }
        }
        sIdx++; if (sIdx >= 3) sIdx -= 3;
    }

    // epilogue
    int g = lane >> 2, t2 = (lane & 3) * 2;
    float* Cp = C + (long)pair * Ss * N;
#pragma unroll
    for (int mt = 0; mt < 4; mt++) {
        int m = m0 + wm * 64 + mt * 16 + g;
#pragma unroll
        for (int nt = 0; nt < 4; nt++) {
            int n = n0 + wn * 32 + nt * 8 + t2;
            *(float2*)(Cp + (long)m * N + n)       = make_float2(acc[mt][nt][0], acc[mt][nt][1]);
            *(float2*)(Cp + (long)(m + 8) * N + n) = make_float2(acc[mt][nt][2], acc[mt][nt][3]);
        }
    }
}

// ---------------- RoPE on q,k heads of g_qkv ----------------
__global__ void rope_kernel(const float* __restrict__ cosb, const float* __restrict__ sinb) {
    int s = blockIdx.x, pair = blockIdx.y;
    int tid = threadIdx.x;
    int hh = tid >> 5, d = tid & 31;
    float* p = g_qkv + ((long)(pair * Ss + s)) * QKVW + hh * HD;
    float x1 = p[d], x2 = p[d + 32];
    float c1 = cosb[s * HD + d],      s1 = sinb[s * HD + d];
    float c2 = cosb[s * HD + d + 32], s2 = sinb[s * HD + d + 32];
    p[d]      = x1 * c1 - x2 * s1;
    p[d + 32] = x2 * c2 + x1 * s2;
}

// ---------------- flash attention ----------------
__global__ void __launch_bounds__(256) attn_kernel() {
    __shared__ float qs[32 * 64];
    __shared__ float kT[64 * 64];
    __shared__ float vs[64 * 64];
    __shared__ float psm[32 * 64];

    int pair = blockIdx.z, head = blockIdx.y, qt = blockIdx.x;
    const float* base = g_qkv + (long)pair * Ss * QKVW;
    int tid = threadIdx.x;
    int warp = tid >> 5, lane = tid & 31;
    int q0 = qt * 32;

#pragma unroll
    for (int i = 0; i < 2; i++) {
        int lin = tid + i * 256;
        int row = lin >> 4;
        int c4 = (lin & 15) * 4;
        float4 v = *(const float4*)(base + (long)(q0 + row) * QKVW + head * HD + c4);
        qs[row * 64 + c4 + 0] = v.x * 0.125f;
        qs[row * 64 + c4 + 1] = v.y * 0.125f;
        qs[row * 64 + c4 + 2] = v.z * 0.125f;
        qs[row * 64 + c4 + 3] = v.w * 0.125f;
    }

    float o[4][2], mrow[4], lrow[4];
#pragma unroll
    for (int r = 0; r < 4; r++) {
        o[r][0] = 0.f; o[r][1] = 0.f; mrow[r] = -1e30f; lrow[r] = 0.f;
    }

    for (int kt = 0; kt < 8; kt++) {
        int k0 = kt * 64;
        __syncthreads();
#pragma unroll
        for (int i = 0; i < 4; i++) {
            int lin = tid + i * 256;
            int key = lin >> 4;
            int c4 = (lin & 15) * 4;
            float4 kv = *(const float4*)(base + (long)(k0 + key) * QKVW + 512 + head * HD + c4);
            kT[(c4 + 0) * 64 + key] = kv.x;
            kT[(c4 + 1) * 64 + key] = kv.y;
            kT[(c4 + 2) * 64 + key] = kv.z;
            kT[(c4 + 3) * 64 + key] = kv.w;
            float4 vv = *(const float4*)(base + (long)(k0 + key) * QKVW + 1024 + head * HD + c4);
            vs[key * 64 + c4 + 0] = vv.x;
            vs[key * 64 + c4 + 1] = vv.y;
            vs[key * 64 + c4 + 2] = vv.z;
            vs[key * 64 + c4 + 3] = vv.w;
        }
        __syncthreads();

        float sreg[4][2];
#pragma unroll
        for (int r = 0; r < 4; r++) { sreg[r][0] = 0.f; sreg[r][1] = 0.f; }
#pragma unroll 4
        for (int kk = 0; kk < 64; kk++) {
            float kv0 = kT[kk * 64 + lane];
            float kv1 = kT[kk * 64 + lane + 32];
#pragma unroll
            for (int r = 0; r < 4; r++) {
                float qv = qs[(warp * 4 + r) * 64 + kk];
                sreg[r][0] += qv * kv0;
                sreg[r][1] += qv * kv1;
            }
        }

#pragma unroll
        for (int r = 0; r < 4; r++) {
            float mx = fmaxf(sreg[r][0], sreg[r][1]);
#pragma unroll
            for (int off = 16; off; off >>= 1) mx = fmaxf(mx, __shfl_xor_sync(0xffffffffu, mx, off));
            float mnew = fmaxf(mrow[r], mx);
            float scale = expf(mrow[r] - mnew);
            float p0 = expf(sreg[r][0] - mnew);
            float p1 = expf(sreg[r][1] - mnew);
            float ls = p0 + p1;
#pragma unroll
            for (int off = 16; off; off >>= 1) ls += __shfl_xor_sync(0xffffffffu, ls, off);
            lrow[r] = lrow[r] * scale + ls;
            mrow[r] = mnew;
            o[r][0] *= scale; o[r][1] *= scale;
            psm[(warp * 4 + r) * 64 + lane] = p0;
            psm[(warp * 4 + r) * 64 + lane + 32] = p1;
        }
        __syncwarp();

#pragma unroll 4
        for (int c = 0; c < 64; c++) {
            float v0 = vs[c * 64 + lane];
            float v1 = vs[c * 64 + lane + 32];
#pragma unroll
            for (int r = 0; r < 4; r++) {
                float pv = psm[(warp * 4 + r) * 64 + c];
                o[r][0] += pv * v0;
                o[r][1] += pv * v1;
            }
        }
        __syncwarp();
    }

#pragma unroll
    for (int r = 0; r < 4; r++) {
        float inv = 1.f / lrow[r];
        long orow = ((long)pair * Ss + q0 + warp * 4 + r) * HSUB + head * HD;
        g_att[orow + lane]      = o[r][0] * inv;
        g_att[orow + lane + 32] = o[r][1] * inv;
    }
}

// ---------------- residual + rmsnorm ----------------
__global__ void resnorm_kernel() {
    long row = blockIdx.x;
    float* a = g_hs + row * HSUB;
    const float* t = g_tmp + row * HSUB;
    int tid = threadIdx.x;
    float v0 = a[tid] + t[tid];
    float v1 = a[tid + 256] + t[tid + 256];
    float ss = v0 * v0 + v1 * v1;
#pragma unroll
    for (int off = 16; off; off >>= 1) ss += __shfl_xor_sync(0xffffffffu, ss, off);
    __shared__ float red[8];
    __shared__ float stot;
    if ((tid & 31) == 0) red[tid >> 5] = ss;
    __syncthreads();
    if (tid == 0) {
        float tsum = 0.f;
        for (int i = 0; i < 8; i++) tsum += red[i];
        stot = tsum;
    }
    __syncthreads();
    float scale = rsqrtf(stot * (1.f / HSUB) + 1e-5f);
    a[tid] = v0 * scale;
    a[tid + 256] = v1 * scale;
}

// ---------------- silu(gate)*up fused with plane conversion -> g_a3 ----------------
__global__ void silu3_kernel(unsigned short* __restrict__ dst) {
    long i = (long)blockIdx.x * 256 + threadIdx.x;     // float4 index over (rows, INTER/4)
    long row = i / (INTER / 4);
    int c4 = (int)(i - row * (INTER / 4));
    const float* gr = g_gu + row * GUW;
    float4 gv = *(const float4*)(gr + c4 * 4);
    float4 uv = *(const float4*)(gr + INTER + c4 * 4);
    float x[4];
    x[0] = gv.x / (1.f + expf(-gv.x)) * uv.x;
    x[1] = gv.y / (1.f + expf(-gv.y)) * uv.y;
    x[2] = gv.z / (1.f + expf(-gv.z)) * uv.z;
    x[3] = gv.w / (1.f + expf(-gv.w)) * uv.w;
    unsigned int h[4], l[4];
#pragma unroll
    for (int j = 0; j < 4; j++) {
        __nv_bfloat16 hb = __float2bfloat16(x[j]);
        float r = x[j] - __bfloat162float(hb);
        __nv_bfloat16 lb = __float2bfloat16(r);
        h[j] = (unsigned int)__bfloat16_as_ushort(hb);
        l[j] = (unsigned int)__bfloat16_as_ushort(lb);
    }
    uint2 uh, ul;
    uh.x = h[0] | (h[1] << 16); uh.y = h[2] | (h[3] << 16);
    ul.x = l[0] | (l[1] << 16); ul.y = l[2] | (l[3] << 16);
    unsigned short* base = dst + row * 3 * INTER + (long)c4 * 4;
    *(uint2*)base = uh;
    *(uint2*)(base + INTER)     = ul;
    *(uint2*)(base + 2 * INTER) = uh;
}

// ---------------- final ----------------
__global__ void final_kernel(float* __restrict__ out) {
    int b = blockIdx.y, s = blockIdx.x;
    float w0 = g_pair_w[2 * b], w1 = g_pair_w[2 * b + 1];
    long r = (long)b * Ss + s;
    const float* hp = g_h + r * Hh;
    const float* u0 = g_up + ((long)(2 * b) * Ss + s) * Hh;
    const float* u1 = g_up + ((long)(2 * b + 1) * Ss + s) * Hh;
    int tid = threadIdx.x;
    int c = tid * 4;
    float4 vh = *(const float4*)(hp + c);
    float4 v0 = *(const float4*)(u0 + c);
    float4 v1 = *(const float4*)(u1 + c);
    float y[4];
    y[0] = vh.x + w0 * v0.x + w1 * v1.x;
    y[1] = vh.y + w0 * v0.y + w1 * v1.y;
    y[2] = vh.z + w0 * v0.z + w1 * v1.z;
    y[3] = vh.w + w0 * v0.w + w1 * v1.w;
    float ss = y[0] * y[0] + y[1] * y[1] + y[2] * y[2] + y[3] * y[3];
#pragma unroll
    for (int off = 16; off; off >>= 1) ss += __shfl_xor_sync(0xffffffffu, ss, off);
    __shared__ float red[8];
    __shared__ float stot;
    if ((tid & 31) == 0) red[tid >> 5] = ss;
    __syncthreads();
    if (tid == 0) {
        float tsum = 0.f;
        for (int i = 0; i < 8; i++) tsum += red[i];
        stot = tsum;
    }
    __syncthreads();
    float scale = rsqrtf(stot * (1.f / Hh) + 1e-5f);
    float4 o;
    o.x = y[0] * scale; o.y = y[1] * scale; o.z = y[2] * scale; o.w = y[3] * scale;
    *(float4*)(out + r * Hh + c) = o;
}

// ---------------- launch ----------------
extern "C" void kernel_launch(void* const* d_in, const int* in_sizes, int n_in,
                              void* d_out, int out_size) {
    const float* hidden     = (const float*)d_in[0];
    const float* inj        = (const float*)d_in[1];
    const float* cosb       = (const float*)d_in[2];
    const float* sinb       = (const float*)d_in[3];
    const float* gate_w     = (const float*)d_in[4];
    const float* down_w     = (const float*)d_in[5];
    const float* up_w       = (const float*)d_in[6];
    const float* qkv_w      = (const float*)d_in[7];
    const float* o_w        = (const float*)d_in[8];
    const float* gate_up_w  = (const float*)d_in[9];
    const float* mlp_down_w = (const float*)d_in[10];
    float* out = (float*)d_out;

    void* vp;
    cudaGetSymbolAddress(&vp, g_h);   float* p_h   = (float*)vp;
    cudaGetSymbolAddress(&vp, g_hs);  float* p_hs  = (float*)vp;
    cudaGetSymbolAddress(&vp, g_qkv); float* p_qkv = (float*)vp;
    cudaGetSymbolAddress(&vp, g_att); float* p_att = (float*)vp;
    cudaGetSymbolAddress(&vp, g_tmp); float* p_tmp = (float*)vp;
    cudaGetSymbolAddress(&vp, g_gu);  float* p_gu  = (float*)vp;
    cudaGetSymbolAddress(&vp, g_up);  float* p_up  = (float*)vp;
    cudaGetSymbolAddress(&vp, g_w3);  unsigned short* p_w3 = (unsigned short*)vp;
    cudaGetSymbolAddress(&vp, g_a3);  unsigned short* p_a3 = (unsigned short*)vp;

    cudaFuncSetAttribute(gemm_mma, cudaFuncAttributeMaxDynamicSharedMemorySize, 3 * GSTAGE_B);

    // weight plane folding (hi/lo 3-term, W-mode)
    cvt3_kernel<<<(int)(4194304L / 4 / 256), 256>>>(down_w,     p_w3 + 3 * OFF_DOWN, 1024 / 4, 0);
    cvt3_kernel<<<(int)(6291456L / 4 / 256), 256>>>(qkv_w,      p_w3 + 3 * OFF_QKV,  512 / 4,  0);
    cvt3_kernel<<<(int)(2097152L / 4 / 256), 256>>>(o_w,        p_w3 + 3 * OFF_O,    512 / 4,  0);
    cvt3_kernel<<<(int)(12582912L / 4 / 256), 256>>>(gate_up_w, p_w3 + 3 * OFF_GU,   512 / 4,  0);
    cvt3_kernel<<<(int)(6291456L / 4 / 256), 256>>>(mlp_down_w, p_w3 + 3 * OFF_MLPD, 1536 / 4, 0);
    cvt3_kernel<<<(int)(4194304L / 4 / 256), 256>>>(up_w,       p_w3 + 3 * OFF_UP,   512 / 4,  0);

    // 1. h = hidden + injection ; routing
    int n4 = Bb * Ss * Hh / 4;
    add_kernel<<<n4 / 256, 256>>>(hidden, inj);
    routing_kernel<<<1, 64>>>(gate_w, out + (out_size - 1));

    // 2. hs0 = h @ down_w^T  (K3=3072, N=512)
    cvt3_kernel<<<(Bb * Ss * Hh / 4) / 256, 256>>>(p_h, p_a3, 1024 / 4, 1);
    gemm_mma<<<dim3(HSUB / 128, 4, NPAIR), 256, 3 * GSTAGE_B>>>(p_a3, 2, p_w3 + 3 * OFF_DOWN, p_hs, 3 * Hh, HSUB);

    // 3. qkv = hs0 @ qkv_w^T  (K3=1536, N=1536)
    cvt3_kernel<<<(NPAIR * Ss * HSUB / 4) / 256, 256>>>(p_hs, p_a3, 512 / 4, 1);
    gemm_mma<<<dim3(QKVW / 128, 4, NPAIR), 256, 3 * GSTAGE_B>>>(p_a3, 1, p_w3 + 3 * OFF_QKV, p_qkv, 3 * HSUB, QKVW);

    // 4. rope + attention
    rope_kernel<<<dim3(Ss, NPAIR), 512>>>(cosb, sinb);
    attn_kernel<<<dim3(16, NHEAD, NPAIR), 256>>>();

    // 5. tmp = att @ o_w^T  (K3=1536, N=512)
    cvt3_kernel<<<(NPAIR * Ss * HSUB / 4) / 256, 256>>>(p_att, p_a3, 512 / 4, 1);
    gemm_mma<<<dim3(HSUB / 128, 4, NPAIR), 256, 3 * GSTAGE_B>>>(p_a3, 1, p_w3 + 3 * OFF_O, p_tmp, 3 * HSUB, HSUB);

    // 6. hs1 = rmsnorm(hs0 + tmp)
    resnorm_kernel<<<NPAIR * Ss, 256>>>();

    // 7. gu = hs1 @ gate_up_w^T  (K3=1536, N=3072)
    cvt3_kernel<<<(NPAIR * Ss * HSUB / 4) / 256, 256>>>(p_hs, p_a3, 512 / 4, 1);
    gemm_mma<<<dim3(GUW / 128, 4, NPAIR), 256, 3 * GSTAGE_B>>>(p_a3, 1, p_w3 + 3 * OFF_GU, p_gu, 3 * HSUB, GUW);

    // 8+9. act = silu(gate)*up fused into planes; tmp = act @ mlp_down_w^T  (K3=4608, N=512)
    silu3_kernel<<<(NPAIR * Ss * INTER / 4) / 256, 256>>>(p_a3);
    gemm_mma<<<dim3(HSUB / 128, 4, NPAIR), 256, 3 * GSTAGE_B>>>(p_a3, 1, p_w3 + 3 * OFF_MLPD, p_tmp, 3 * INTER, HSUB);

    // 10. hs2 = rmsnorm(hs1 + tmp)
    resnorm_kernel<<<NPAIR * Ss, 256>>>();

    // 11. up_out = hs2 @ up_w^T  (K3=1536, N=1024)
    cvt3_kernel<<<(NPAIR * Ss * HSUB / 4) / 256, 256>>>(p_hs, p_a3, 512 / 4, 1);
    gemm_mma<<<dim3(Hh / 128, 4, NPAIR), 256, 3 * GSTAGE_B>>>(p_a3, 1, p_w3 + 3 * OFF_UP, p_up, 3 * HSUB, Hh);

    // 12. out = rmsnorm(h + w0*u0 + w1*u1)
    final_kernel<<<dim3(Ss, Bb), 256>>>(out);
}

// round 5
// speedup vs baseline: 2.6531x; 1.3278x over previous
#include <cuda_runtime.h>
#include <cuda_bf16.h>
#include <math.h>
#include <stdint.h>

#define Bb 8
#define Ss 512
#define Hh 1024
#define Ee 8
#define NHEAD 8
#define HD 64
#define HSUB 512
#define INTER 1536
#define NPAIR 16
#define QKVW 1536
#define GUW 3072

// ---------------- scratch ----------------
__device__ float g_h[Bb * Ss * Hh];
__device__ float g_hs[NPAIR * Ss * HSUB];
__device__ float g_qkv[NPAIR * Ss * QKVW];
__device__ float g_att[NPAIR * Ss * HSUB];
__device__ float g_tmp[NPAIR * Ss * HSUB];
__device__ float g_gu[NPAIR * Ss * GUW];
__device__ float g_up[NPAIR * Ss * Hh];
__device__ int   g_pair_e[NPAIR];
__device__ float g_pair_w[NPAIR];

#define OFF_DOWN 0L
#define OFF_QKV  4194304L
#define OFF_O    10485760L
#define OFF_GU   12582912L
#define OFF_MLPD 25165824L
#define OFF_UP   31457280L
#define W_TOTAL  35651584L
__device__ unsigned short g_w3[W_TOTAL * 3];
__device__ unsigned short g_a3[NPAIR * Ss * INTER * 3];

// attention workspace offsets inside g_a3 (ushort elems), 6 x 4194304
#define WQH 0L
#define WQL 4194304L
#define WKH 8388608L
#define WKL 12582912L
#define WVH 16777216L
#define WVL 20971520L

// ---------------- PTX helpers ----------------
__device__ __forceinline__ uint32_t smem_u32(const void* p) {
    uint32_t a;
    asm("{ .reg .u64 t; cvta.to.shared.u64 t, %1; cvt.u32.u64 %0, t; }" : "=r"(a) : "l"(p));
    return a;
}
#define CP_ASYNC(sm, gp) asm volatile("cp.async.cg.shared.global [%0], [%1], 16;" :: "r"(sm), "l"(gp))
#define CP_COMMIT()      asm volatile("cp.async.commit_group;" ::: "memory")
#define CP_WAIT1()       asm volatile("cp.async.wait_group 1;" ::: "memory")
#define LDMX4(r0, r1, r2, r3, a) \
    asm volatile("ldmatrix.sync.aligned.m8n8.x4.shared.b16 {%0,%1,%2,%3}, [%4];" \
        : "=r"(r0), "=r"(r1), "=r"(r2), "=r"(r3) : "r"(a))
#define MMA16816(d, a0, a1, a2, a3, b0, b1) \
    asm volatile("mma.sync.aligned.m16n8k16.row.col.f32.bf16.bf16.f32 " \
        "{%0,%1,%2,%3}, {%4,%5,%6,%7}, {%8,%9}, {%0,%1,%2,%3};" \
        : "+f"((d)[0]), "+f"((d)[1]), "+f"((d)[2]), "+f"((d)[3]) \
        : "r"(a0), "r"(a1), "r"(a2), "r"(a3), "r"(b0), "r"(b1))

__device__ __forceinline__ void split2(float x, unsigned short& h, unsigned short& l) {
    __nv_bfloat16 hb = __float2bfloat16(x);
    h = __bfloat16_as_ushort(hb);
    l = __bfloat16_as_ushort(__float2bfloat16(x - __bfloat162float(hb)));
}

// ---------------- elementwise: h = hidden + injection ----------------
__global__ void add_kernel(const float* __restrict__ a, const float* __restrict__ b) {
    int i = blockIdx.x * 256 + threadIdx.x;
    float4 va = ((const float4*)a)[i];
    float4 vb = ((const float4*)b)[i];
    float4 o;
    o.x = va.x + vb.x; o.y = va.y + vb.y; o.z = va.z + vb.z; o.w = va.w + vb.w;
    ((float4*)g_h)[i] = o;
}

// ---------------- fp32 -> folded 3-term bf16 planes ----------------
__global__ void cvt3_kernel(const float* __restrict__ src,
                            unsigned short* __restrict__ dst,
                            int K4, int modeA) {
    long i = (long)blockIdx.x * 256 + threadIdx.x;
    long row = i / K4;
    int kc = (int)(i - row * K4);
    float4 v = ((const float4*)src)[i];
    float x[4] = {v.x, v.y, v.z, v.w};
    unsigned int h[4], l[4];
#pragma unroll
    for (int j = 0; j < 4; j++) {
        unsigned short hs_, ls_;
        split2(x[j], hs_, ls_);
        h[j] = hs_; l[j] = ls_;
    }
    uint2 uh, ul;
    uh.x = h[0] | (h[1] << 16); uh.y = h[2] | (h[3] << 16);
    ul.x = l[0] | (l[1] << 16); ul.y = l[2] | (l[3] << 16);
    long K = (long)K4 * 4;
    unsigned short* base = dst + row * 3 * K + (long)kc * 4;
    *(uint2*)base = uh;
    if (modeA) {
        *(uint2*)(base + K)     = ul;
        *(uint2*)(base + 2 * K) = uh;
    } else {
        *(uint2*)(base + K)     = uh;
        *(uint2*)(base + 2 * K) = ul;
    }
}

// ---------------- routing ----------------
__global__ void routing_kernel(const float* __restrict__ gate_w, float* __restrict__ aux_out) {
    __shared__ float logits[Bb][Ee];
    __shared__ float probs[Bb][Ee];
    int tid = threadIdx.x;
    if (tid < Bb * Ee) {
        int b = tid >> 3, e = tid & 7;
        const float* hv = g_h + (long)b * Ss * Hh;
        const float* w = gate_w + e * Hh;
        float acc = 0.f;
        for (int i = 0; i < Hh; i++) acc += hv[i] * w[i];
        logits[b][e] = acc;
    }
    __syncthreads();
    if (tid < Bb) {
        int b = tid;
        float mx = -1e30f;
        for (int e = 0; e < Ee; e++) mx = fmaxf(mx, logits[b][e]);
        float p[Ee]; float sum = 0.f;
        for (int e = 0; e < Ee; e++) { p[e] = expf(logits[b][e] - mx); sum += p[e]; }
        for (int e = 0; e < Ee; e++) { p[e] /= sum; probs[b][e] = p[e]; }
        int i1 = 0;
        for (int e = 1; e < Ee; e++) if (p[e] > p[i1]) i1 = e;
        int i2 = -1; float v2 = -1e30f;
        for (int e = 0; e < Ee; e++) if (e != i1 && p[e] > v2) { v2 = p[e]; i2 = e; }
        float denom = fmaxf(p[i1] + v2, 1e-8f);
        g_pair_e[2 * b]     = i1; g_pair_w[2 * b]     = p[i1] / denom;
        g_pair_e[2 * b + 1] = i2; g_pair_w[2 * b + 1] = v2 / denom;
    }
    __syncthreads();
    if (tid == 0) {
        float aux = 0.f;
        for (int e = 0; e < Ee; e++) {
            float imp = 0.f;
            for (int b = 0; b < Bb; b++) imp += probs[b][e];
            imp /= (float)Bb;
            int cnt = 0;
            for (int p = 0; p < NPAIR; p++) if (g_pair_e[p] == e) cnt++;
            float loadf = (float)cnt / (float)(Bb * 2);
            aux += (float)Ee * imp * loadf;
        }
        *aux_out = aux;
    }
}

// ---------------- mma.sync bf16 GEMM, cp.async + ldmatrix, BK=64, 3-stage ----------------
#define GSTAGE_B 32768
#define GB_OFF   16384

__global__ void __launch_bounds__(256, 2) gemm_mma(
    const unsigned short* __restrict__ A, int aDiv,
    const unsigned short* __restrict__ W,
    float* __restrict__ C, int K3, int N)
{
    extern __shared__ __align__(1024) char sm[];
    uint32_t sb = smem_u32(sm);

    int tid = threadIdx.x;
    int wid = tid >> 5, lane = tid & 31;
    int wm = wid & 1, wn = wid >> 1;
    int pair = blockIdx.z;
    int m0 = blockIdx.y * 128, n0 = blockIdx.x * 128;

    const unsigned short* gA = A + (long)(pair / aDiv) * Ss * K3 + (long)m0 * K3;
    const unsigned short* gW = W + (long)g_pair_e[pair] * N * K3 + (long)n0 * K3;

    int ldRow = tid >> 3, ldC = tid & 7;
    uint32_t soff[4];
    const unsigned short* gAp[4];
    const unsigned short* gWp[4];
#pragma unroll
    for (int j = 0; j < 4; j++) {
        int row = ldRow + 32 * j;
        soff[j] = row * 128 + ((ldC ^ (row & 7)) << 4);
        gAp[j] = gA + (long)row * K3 + ldC * 8;
        gWp[j] = gW + (long)row * K3 + ldC * 8;
    }

    int l8 = lane & 7;
    int rowA = l8 + 8 * ((lane >> 3) & 1);
    int cA = lane >> 4;
    int rowB = l8 + 8 * (lane >> 4);
    int cB = (lane >> 3) & 1;
    uint32_t aRowOff = (uint32_t)(wm * 64 + rowA) * 128;
    uint32_t bRowOff = (uint32_t)(wn * 32 + rowB) * 128 + GB_OFF;

    float acc[4][4][4];
#pragma unroll
    for (int i = 0; i < 4; i++)
#pragma unroll
        for (int j = 0; j < 4; j++)
#pragma unroll
            for (int k = 0; k < 4; k++) acc[i][j][k] = 0.f;

    int nc = K3 >> 6;

#pragma unroll
    for (int s = 0; s < 2; s++) {
        uint32_t st = sb + s * GSTAGE_B;
        long kb = (long)s * 64;
#pragma unroll
        for (int j = 0; j < 4; j++) {
            CP_ASYNC(st + soff[j], gAp[j] + kb);
            CP_ASYNC(st + GB_OFF + soff[j], gWp[j] + kb);
        }
        CP_COMMIT();
    }

    int sIdx = 0;
    for (int c = 0; c < nc; c++) {
        CP_WAIT1();
        __syncthreads();
        if (c + 2 < nc) {
            int s2 = sIdx + 2; if (s2 >= 3) s2 -= 3;
            uint32_t st = sb + s2 * GSTAGE_B;
            long kb = (long)(c + 2) * 64;
#pragma unroll
            for (int j = 0; j < 4; j++) {
                CP_ASYNC(st + soff[j], gAp[j] + kb);
                CP_ASYNC(st + GB_OFF + soff[j], gWp[j] + kb);
            }
            CP_COMMIT();
        } else {
            CP_COMMIT();
        }

        uint32_t stA = sb + sIdx * GSTAGE_B + aRowOff;
        uint32_t stB = sb + sIdx * GSTAGE_B + bRowOff;
#pragma unroll
        for (int kk = 0; kk < 4; kk++) {
            unsigned af[4][4], bf[4][2];
            uint32_t kxA = (uint32_t)(((2 * kk + cA) ^ l8) << 4);
            uint32_t kxB = (uint32_t)(((2 * kk + cB) ^ l8) << 4);
#pragma unroll
            for (int mt = 0; mt < 4; mt++)
                LDMX4(af[mt][0], af[mt][1], af[mt][2], af[mt][3], stA + mt * 2048 + kxA);
            LDMX4(bf[0][0], bf[0][1], bf[1][0], bf[1][1], stB + kxB);
            LDMX4(bf[2][0], bf[2][1], bf[3][0], bf[3][1], stB + 2048 + kxB);
#pragma unroll
            for (int mt = 0; mt < 4; mt++)
#pragma unroll
                for (int nt = 0; nt < 4; nt++)
                    MMA16816(acc[mt][nt], af[mt][0], af[mt][1], af[mt][2], af[mt][3],
                             bf[nt][0], bf[nt][1]);
        }
        sIdx++; if (sIdx >= 3) sIdx -= 3;
    }

    int g = lane >> 2, t2 = (lane & 3) * 2;
    float* Cp = C + (long)pair * Ss * N;
#pragma unroll
    for (int mt = 0; mt < 4; mt++) {
        int m = m0 + wm * 64 + mt * 16 + g;
#pragma unroll
        for (int nt = 0; nt < 4; nt++) {
            int n = n0 + wn * 32 + nt * 8 + t2;
            *(float2*)(Cp + (long)m * N + n)       = make_float2(acc[mt][nt][0], acc[mt][nt][1]);
            *(float2*)(Cp + (long)(m + 8) * N + n) = make_float2(acc[mt][nt][2], acc[mt][nt][3]);
        }
    }
}

// ---------------- prep attention: rope + scale + hi/lo split + V transpose ----------------
// grid (Ss, NPAIR), 256 threads (8 heads x 32 dims)
__global__ void prep_attn(const float* __restrict__ cosb, const float* __restrict__ sinb,
                          unsigned short* __restrict__ ws) {
    int s = blockIdx.x, pair = blockIdx.y;
    int tid = threadIdx.x;
    int hh = tid >> 5, d = tid & 31;
    const float* base = g_qkv + ((long)pair * Ss + s) * QKVW;
    long ph = (long)pair * 8 + hh;
    float c1 = cosb[s * HD + d],      s1 = sinb[s * HD + d];
    float c2 = cosb[s * HD + d + 32], s2 = sinb[s * HD + d + 32];
    // q (scaled by 1/8)
    {
        float x1 = base[hh * HD + d], x2 = base[hh * HD + d + 32];
        float y1 = (x1 * c1 - x2 * s1) * 0.125f;
        float y2 = (x2 * c2 + x1 * s2) * 0.125f;
        long o = (ph * Ss + s) * HD + d;
        unsigned short h0, l0, h1, l1;
        split2(y1, h0, l0); split2(y2, h1, l1);
        g_a3[WQH + o] = h0; g_a3[WQL + o] = l0;
        g_a3[WQH + o + 32] = h1; g_a3[WQL + o + 32] = l1;
    }
    // k
    {
        float x1 = base[512 + hh * HD + d], x2 = base[512 + hh * HD + d + 32];
        float y1 = x1 * c1 - x2 * s1;
        float y2 = x2 * c2 + x1 * s2;
        long o = (ph * Ss + s) * HD + d;
        unsigned short h0, l0, h1, l1;
        split2(y1, h0, l0); split2(y2, h1, l1);
        g_a3[WKH + o] = h0; g_a3[WKL + o] = l0;
        g_a3[WKH + o + 32] = h1; g_a3[WKL + o + 32] = l1;
    }
    // v (transposed [d][s])
    {
        float v1 = base[1024 + hh * HD + d], v2 = base[1024 + hh * HD + d + 32];
        long o1 = (ph * HD + d) * Ss + s;
        long o2 = (ph * HD + d + 32) * Ss + s;
        unsigned short h0, l0, h1, l1;
        split2(v1, h0, l0); split2(v2, h1, l1);
        g_a3[WVH + o1] = h0; g_a3[WVL + o1] = l0;
        g_a3[WVH + o2] = h1; g_a3[WVL + o2] = l1;
    }
}

// ---------------- mma flash attention: 128 q-rows/block, 8 warps ----------------
// smem: Qh 16K | Ql 16K | 2 stages x (Kh 8K | Kl 8K | Vh 8K | Vl 8K) = 96KB
#define ASMEM 98304

__global__ void __launch_bounds__(256) attn_mma(const unsigned short* __restrict__ ws) {
    extern __shared__ __align__(1024) char sm2[];
    uint32_t sb = smem_u32(sm2);
    int tid = threadIdx.x, w = tid >> 5, lane = tid & 31;
    int qt = blockIdx.x, head = blockIdx.y, pair = blockIdx.z;
    int q0 = qt * 128;
    long ph = (long)pair * 8 + head;
    const unsigned short* Qh = ws + WQH + ph * Ss * HD;
    const unsigned short* Ql = ws + WQL + ph * Ss * HD;
    const unsigned short* Kh = ws + WKH + ph * Ss * HD;
    const unsigned short* Kl = ws + WKL + ph * Ss * HD;
    const unsigned short* Vh = ws + WVH + ph * HD * Ss;
    const unsigned short* Vl = ws + WVL + ph * HD * Ss;

    int ldRow = tid >> 3, ldC = tid & 7;

    // Q planes
#pragma unroll
    for (int j = 0; j < 4; j++) {
        int row = ldRow + 32 * j;
        uint32_t so = row * 128 + ((ldC ^ (row & 7)) << 4);
        CP_ASYNC(sb + so,         Qh + (long)(q0 + row) * HD + ldC * 8);
        CP_ASYNC(sb + 16384 + so, Ql + (long)(q0 + row) * HD + ldC * 8);
    }
    auto issue = [&](int buf, int kt) {
        uint32_t st = sb + 32768 + buf * 32768;
#pragma unroll
        for (int j = 0; j < 2; j++) {
            int row = ldRow + 32 * j;
            uint32_t so = row * 128 + ((ldC ^ (row & 7)) << 4);
            long kOff = (long)(kt * 64 + row) * HD + ldC * 8;
            CP_ASYNC(st + so,         Kh + kOff);
            CP_ASYNC(st + 8192 + so,  Kl + kOff);
            long vOff = (long)row * Ss + kt * 64 + ldC * 8;
            CP_ASYNC(st + 16384 + so, Vh + vOff);
            CP_ASYNC(st + 24576 + so, Vl + vOff);
        }
    };
    issue(0, 0); CP_COMMIT();
    issue(1, 1); CP_COMMIT();

    int l8 = lane & 7;
    int rowA = l8 + 8 * ((lane >> 3) & 1);
    int cA = lane >> 4;
    int rowB = l8 + 8 * (lane >> 4);
    int cB = (lane >> 3) & 1;
    uint32_t aOff = (uint32_t)(w * 16 + rowA) * 128;
    uint32_t bOff = (uint32_t)rowB * 128;

    float o[8][4];
#pragma unroll
    for (int f = 0; f < 8; f++)
#pragma unroll
        for (int k = 0; k < 4; k++) o[f][k] = 0.f;
    float mr[2] = {-1e30f, -1e30f}, lr[2] = {0.f, 0.f};

    for (int kt = 0; kt < 8; kt++) {
        CP_WAIT1();
        __syncthreads();
        int buf = kt & 1;
        uint32_t st = sb + 32768 + buf * 32768;

        // --- scores: 3 passes ---
        float sc[8][4];
#pragma unroll
        for (int f = 0; f < 8; f++)
#pragma unroll
            for (int k = 0; k < 4; k++) sc[f][k] = 0.f;
#pragma unroll
        for (int pass = 0; pass < 3; pass++) {
            uint32_t aB = sb + (pass == 1 ? 16384u : 0u) + aOff;
            uint32_t bB = st + (pass == 2 ? 8192u : 0u) + bOff;
#pragma unroll
            for (int kk = 0; kk < 4; kk++) {
                unsigned af[4], bfr[8][2];
                uint32_t kxA = (uint32_t)(((2 * kk + cA) ^ l8) << 4);
                uint32_t kxB = (uint32_t)(((2 * kk + cB) ^ l8) << 4);
                LDMX4(af[0], af[1], af[2], af[3], aB + kxA);
#pragma unroll
                for (int n2 = 0; n2 < 4; n2++)
                    LDMX4(bfr[2*n2][0], bfr[2*n2][1], bfr[2*n2+1][0], bfr[2*n2+1][1],
                          bB + n2 * 2048 + kxB);
#pragma unroll
                for (int nt = 0; nt < 8; nt++)
                    MMA16816(sc[nt], af[0], af[1], af[2], af[3], bfr[nt][0], bfr[nt][1]);
            }
        }

        // --- online softmax ---
#pragma unroll
        for (int r = 0; r < 2; r++) {
            float mx = -1e30f;
#pragma unroll
            for (int f = 0; f < 8; f++) mx = fmaxf(mx, fmaxf(sc[f][2*r], sc[f][2*r+1]));
            mx = fmaxf(mx, __shfl_xor_sync(0xffffffffu, mx, 1));
            mx = fmaxf(mx, __shfl_xor_sync(0xffffffffu, mx, 2));
            float mn = fmaxf(mr[r], mx);
            float scale = expf(mr[r] - mn);
            mr[r] = mn;
            float ls = 0.f;
#pragma unroll
            for (int f = 0; f < 8; f++) {
                float p0 = expf(sc[f][2*r] - mn);
                float p1 = expf(sc[f][2*r+1] - mn);
                sc[f][2*r] = p0; sc[f][2*r+1] = p1;
                ls += p0 + p1;
            }
            ls += __shfl_xor_sync(0xffffffffu, ls, 1);
            ls += __shfl_xor_sync(0xffffffffu, ls, 2);
            lr[r] = lr[r] * scale + ls;
#pragma unroll
            for (int f = 0; f < 8; f++) { o[f][2*r] *= scale; o[f][2*r+1] *= scale; }
        }

        // --- split P into hi/lo A-fragments ---
        unsigned aPh[4][4], aPl[4][4];
#pragma unroll
        for (int j = 0; j < 4; j++) {
#pragma unroll
            for (int u = 0; u < 4; u++) {
                int f = 2 * j + (u >> 1);
                int c = (u & 1) * 2;
                unsigned short h0, l0, h1, l1;
                split2(sc[f][c], h0, l0);
                split2(sc[f][c + 1], h1, l1);
                aPh[j][u] = (unsigned)h0 | ((unsigned)h1 << 16);
                aPl[j][u] = (unsigned)l0 | ((unsigned)l1 << 16);
            }
        }

        // --- PV: 3 passes ---
#pragma unroll
        for (int pass = 0; pass < 3; pass++) {
            uint32_t vB = st + (pass == 2 ? 24576u : 16384u) + bOff;
#pragma unroll
            for (int j = 0; j < 4; j++) {
                unsigned bfr[8][2];
                uint32_t kxB = (uint32_t)(((2 * j + cB) ^ l8) << 4);
#pragma unroll
                for (int n2 = 0; n2 < 4; n2++)
                    LDMX4(bfr[2*n2][0], bfr[2*n2][1], bfr[2*n2+1][0], bfr[2*n2+1][1],
                          vB + n2 * 2048 + kxB);
                const unsigned (*aP)[4] = (pass == 1) ? aPl : aPh;
#pragma unroll
                for (int nt = 0; nt < 8; nt++)
                    MMA16816(o[nt], aP[j][0], aP[j][1], aP[j][2], aP[j][3],
                             bfr[nt][0], bfr[nt][1]);
            }
        }
        __syncthreads();
        if (kt + 2 < 8) issue(buf, kt + 2);
        CP_COMMIT();
    }

    // --- store ---
    int g = lane >> 2, t2 = (lane & 3) * 2;
#pragma unroll
    for (int r = 0; r < 2; r++) {
        float inv = 1.f / lr[r];
        long row = (long)pair * Ss + q0 + w * 16 + g + 8 * r;
#pragma unroll
        for (int nt = 0; nt < 8; nt++) {
            *(float2*)(g_att + row * HSUB + head * HD + nt * 8 + t2) =
                make_float2(o[nt][2*r] * inv, o[nt][2*r+1] * inv);
        }
    }
}

// ---------------- residual + rmsnorm ----------------
__global__ void resnorm_kernel() {
    long row = blockIdx.x;
    float* a = g_hs + row * HSUB;
    const float* t = g_tmp + row * HSUB;
    int tid = threadIdx.x;
    float v0 = a[tid] + t[tid];
    float v1 = a[tid + 256] + t[tid + 256];
    float ss = v0 * v0 + v1 * v1;
#pragma unroll
    for (int off = 16; off; off >>= 1) ss += __shfl_xor_sync(0xffffffffu, ss, off);
    __shared__ float red[8];
    __shared__ float stot;
    if ((tid & 31) == 0) red[tid >> 5] = ss;
    __syncthreads();
    if (tid == 0) {
        float tsum = 0.f;
        for (int i = 0; i < 8; i++) tsum += red[i];
        stot = tsum;
    }
    __syncthreads();
    float scale = rsqrtf(stot * (1.f / HSUB) + 1e-5f);
    a[tid] = v0 * scale;
    a[tid + 256] = v1 * scale;
}

// ---------------- silu(gate)*up fused with plane conversion -> g_a3 ----------------
__global__ void silu3_kernel(unsigned short* __restrict__ dst) {
    long i = (long)blockIdx.x * 256 + threadIdx.x;
    long row = i / (INTER / 4);
    int c4 = (int)(i - row * (INTER / 4));
    const float* gr = g_gu + row * GUW;
    float4 gv = *(const float4*)(gr + c4 * 4);
    float4 uv = *(const float4*)(gr + INTER + c4 * 4);
    float x[4];
    x[0] = gv.x / (1.f + expf(-gv.x)) * uv.x;
    x[1] = gv.y / (1.f + expf(-gv.y)) * uv.y;
    x[2] = gv.z / (1.f + expf(-gv.z)) * uv.z;
    x[3] = gv.w / (1.f + expf(-gv.w)) * uv.w;
    unsigned int h[4], l[4];
#pragma unroll
    for (int j = 0; j < 4; j++) {
        unsigned short hs_, ls_;
        split2(x[j], hs_, ls_);
        h[j] = hs_; l[j] = ls_;
    }
    uint2 uh, ul;
    uh.x = h[0] | (h[1] << 16); uh.y = h[2] | (h[3] << 16);
    ul.x = l[0] | (l[1] << 16); ul.y = l[2] | (l[3] << 16);
    unsigned short* base = dst + row * 3 * INTER + (long)c4 * 4;
    *(uint2*)base = uh;
    *(uint2*)(base + INTER)     = ul;
    *(uint2*)(base + 2 * INTER) = uh;
}

// ---------------- final ----------------
__global__ void final_kernel(float* __restrict__ out) {
    int b = blockIdx.y, s = blockIdx.x;
    float w0 = g_pair_w[2 * b], w1 = g_pair_w[2 * b + 1];
    long r = (long)b * Ss + s;
    const float* hp = g_h + r * Hh;
    const float* u0 = g_up + ((long)(2 * b) * Ss + s) * Hh;
    const float* u1 = g_up + ((long)(2 * b + 1) * Ss + s) * Hh;
    int tid = threadIdx.x;
    int c = tid * 4;
    float4 vh = *(const float4*)(hp + c);
    float4 v0 = *(const float4*)(u0 + c);
    float4 v1 = *(const float4*)(u1 + c);
    float y[4];
    y[0] = vh.x + w0 * v0.x + w1 * v1.x;
    y[1] = vh.y + w0 * v0.y + w1 * v1.y;
    y[2] = vh.z + w0 * v0.z + w1 * v1.z;
    y[3] = vh.w + w0 * v0.w + w1 * v1.w;
    float ss = y[0] * y[0] + y[1] * y[1] + y[2] * y[2] + y[3] * y[3];
#pragma unroll
    for (int off = 16; off; off >>= 1) ss += __shfl_xor_sync(0xffffffffu, ss, off);
    __shared__ float red[8];
    __shared__ float stot;
    if ((tid & 31) == 0) red[tid >> 5] = ss;
    __syncthreads();
    if (tid == 0) {
        float tsum = 0.f;
        for (int i = 0; i < 8; i++) tsum += red[i];
        stot = tsum;
    }
    __syncthreads();
    float scale = rsqrtf(stot * (1.f / Hh) + 1e-5f);
    float4 o;
    o.x = y[0] * scale; o.y = y[1] * scale; o.z = y[2] * scale; o.w = y[3] * scale;
    *(float4*)(out + r * Hh + c) = o;
}

// ---------------- launch ----------------
extern "C" void kernel_launch(void* const* d_in, const int* in_sizes, int n_in,
                              void* d_out, int out_size) {
    const float* hidden     = (const float*)d_in[0];
    const float* inj        = (const float*)d_in[1];
    const float* cosb       = (const float*)d_in[2];
    const float* sinb       = (const float*)d_in[3];
    const float* gate_w     = (const float*)d_in[4];
    const float* down_w     = (const float*)d_in[5];
    const float* up_w       = (const float*)d_in[6];
    const float* qkv_w      = (const float*)d_in[7];
    const float* o_w        = (const float*)d_in[8];
    const float* gate_up_w  = (const float*)d_in[9];
    const float* mlp_down_w = (const float*)d_in[10];
    float* out = (float*)d_out;

    void* vp;
    cudaGetSymbolAddress(&vp, g_h);   float* p_h   = (float*)vp;
    cudaGetSymbolAddress(&vp, g_hs);  float* p_hs  = (float*)vp;
    cudaGetSymbolAddress(&vp, g_qkv); float* p_qkv = (float*)vp;
    cudaGetSymbolAddress(&vp, g_att); float* p_att = (float*)vp;
    cudaGetSymbolAddress(&vp, g_tmp); float* p_tmp = (float*)vp;
    cudaGetSymbolAddress(&vp, g_gu);  float* p_gu  = (float*)vp;
    cudaGetSymbolAddress(&vp, g_up);  float* p_up  = (float*)vp;
    cudaGetSymbolAddress(&vp, g_w3);  unsigned short* p_w3 = (unsigned short*)vp;
    cudaGetSymbolAddress(&vp, g_a3);  unsigned short* p_a3 = (unsigned short*)vp;

    cudaFuncSetAttribute(gemm_mma, cudaFuncAttributeMaxDynamicSharedMemorySize, 3 * GSTAGE_B);
    cudaFuncSetAttribute(attn_mma, cudaFuncAttributeMaxDynamicSharedMemorySize, ASMEM);

    // weight plane folding
    cvt3_kernel<<<(int)(4194304L / 4 / 256), 256>>>(down_w,     p_w3 + 3 * OFF_DOWN, 1024 / 4, 0);
    cvt3_kernel<<<(int)(6291456L / 4 / 256), 256>>>(qkv_w,      p_w3 + 3 * OFF_QKV,  512 / 4,  0);
    cvt3_kernel<<<(int)(2097152L / 4 / 256), 256>>>(o_w,        p_w3 + 3 * OFF_O,    512 / 4,  0);
    cvt3_kernel<<<(int)(12582912L / 4 / 256), 256>>>(gate_up_w, p_w3 + 3 * OFF_GU,   512 / 4,  0);
    cvt3_kernel<<<(int)(6291456L / 4 / 256), 256>>>(mlp_down_w, p_w3 + 3 * OFF_MLPD, 1536 / 4, 0);
    cvt3_kernel<<<(int)(4194304L / 4 / 256), 256>>>(up_w,       p_w3 + 3 * OFF_UP,   512 / 4,  0);

    // 1. h = hidden + injection ; routing
    int n4 = Bb * Ss * Hh / 4;
    add_kernel<<<n4 / 256, 256>>>(hidden, inj);
    routing_kernel<<<1, 64>>>(gate_w, out + (out_size - 1));

    // 2. hs0 = h @ down_w^T
    cvt3_kernel<<<(Bb * Ss * Hh / 4) / 256, 256>>>(p_h, p_a3, 1024 / 4, 1);
    gemm_mma<<<dim3(HSUB / 128, 4, NPAIR), 256, 3 * GSTAGE_B>>>(p_a3, 2, p_w3 + 3 * OFF_DOWN, p_hs, 3 * Hh, HSUB);

    // 3. qkv = hs0 @ qkv_w^T
    cvt3_kernel<<<(NPAIR * Ss * HSUB / 4) / 256, 256>>>(p_hs, p_a3, 512 / 4, 1);
    gemm_mma<<<dim3(QKVW / 128, 4, NPAIR), 256, 3 * GSTAGE_B>>>(p_a3, 1, p_w3 + 3 * OFF_QKV, p_qkv, 3 * HSUB, QKVW);

    // 4. prep (rope fused) + mma attention
    prep_attn<<<dim3(Ss, NPAIR), 256>>>(cosb, sinb, p_a3);
    attn_mma<<<dim3(4, NHEAD, NPAIR), 256, ASMEM>>>(p_a3);

    // 5. tmp = att @ o_w^T
    cvt3_kernel<<<(NPAIR * Ss * HSUB / 4) / 256, 256>>>(p_att, p_a3, 512 / 4, 1);
    gemm_mma<<<dim3(HSUB / 128, 4, NPAIR), 256, 3 * GSTAGE_B>>>(p_a3, 1, p_w3 + 3 * OFF_O, p_tmp, 3 * HSUB, HSUB);

    // 6. hs1 = rmsnorm(hs0 + tmp)
    resnorm_kernel<<<NPAIR * Ss, 256>>>();

    // 7. gu = hs1 @ gate_up_w^T
    cvt3_kernel<<<(NPAIR * Ss * HSUB / 4) / 256, 256>>>(p_hs, p_a3, 512 / 4, 1);
    gemm_mma<<<dim3(GUW / 128, 4, NPAIR), 256, 3 * GSTAGE_B>>>(p_a3, 1, p_w3 + 3 * OFF_GU, p_gu, 3 * HSUB, GUW);

    // 8+9. act = silu(gate)*up -> planes; tmp = act @ mlp_down_w^T
    silu3_kernel<<<(NPAIR * Ss * INTER / 4) / 256, 256>>>(p_a3);
    gemm_mma<<<dim3(HSUB / 128, 4, NPAIR), 256, 3 * GSTAGE_B>>>(p_a3, 1, p_w3 + 3 * OFF_MLPD, p_tmp, 3 * INTER, HSUB);

    // 10. hs2 = rmsnorm(hs1 + tmp)
    resnorm_kernel<<<NPAIR * Ss, 256>>>();

    // 11. up_out = hs2 @ up_w^T
    cvt3_kernel<<<(NPAIR * Ss * HSUB / 4) / 256, 256>>>(p_hs, p_a3, 512 / 4, 1);
    gemm_mma<<<dim3(Hh / 128, 4, NPAIR), 256, 3 * GSTAGE_B>>>(p_a3, 1, p_w3 + 3 * OFF_UP, p_up, 3 * HSUB, Hh);

    // 12. out = rmsnorm(h + w0*u0 + w1*u1)
    final_kernel<<<dim3(Ss, Bb), 256>>>(out);
}

// round 6
// speedup vs baseline: 2.7010x; 1.0180x over previous
#include <cuda_runtime.h>
#include <cuda_bf16.h>
#include <math.h>
#include <stdint.h>

#define Bb 8
#define Ss 512
#define Hh 1024
#define Ee 8
#define NHEAD 8
#define HD 64
#define HSUB 512
#define INTER 1536
#define NPAIR 16
#define QKVW 1536
#define GUW 3072

// ---------------- scratch ----------------
__device__ float g_h[Bb * Ss * Hh];
__device__ float g_hs[NPAIR * Ss * HSUB];
__device__ float g_qkv[NPAIR * Ss * QKVW];
__device__ float g_tmp[NPAIR * Ss * HSUB];
__device__ float g_gu[NPAIR * Ss * GUW];
__device__ float g_up[NPAIR * Ss * Hh];
__device__ int   g_pair_e[NPAIR];
__device__ float g_pair_w[NPAIR];

#define OFF_DOWN 0L
#define OFF_QKV  4194304L
#define OFF_O    10485760L
#define OFF_GU   12582912L
#define OFF_MLPD 25165824L
#define OFF_UP   31457280L
#define W_TOTAL  35651584L
__device__ unsigned short g_wh[W_TOTAL];
__device__ unsigned short g_wl[W_TOTAL];
// ping-pong activation plane buffers
__device__ unsigned short g_p0h[NPAIR * Ss * INTER];
__device__ unsigned short g_p0l[NPAIR * Ss * INTER];
__device__ unsigned short g_p1h[NPAIR * Ss * INTER];
__device__ unsigned short g_p1l[NPAIR * Ss * INTER];
// attention workspace: 6 planes of 16*8*512*64
#define AWP 4194304L
__device__ unsigned short g_aw[6 * AWP];
#define WQH 0L
#define WQL (1*AWP)
#define WKH (2*AWP)
#define WKL (3*AWP)
#define WVH (4*AWP)
#define WVL (5*AWP)

// ---------------- PTX helpers ----------------
__device__ __forceinline__ uint32_t smem_u32(const void* p) {
    uint32_t a;
    asm("{ .reg .u64 t; cvta.to.shared.u64 t, %1; cvt.u32.u64 %0, t; }" : "=r"(a) : "l"(p));
    return a;
}
#define CP_ASYNC(sm, gp) asm volatile("cp.async.cg.shared.global [%0], [%1], 16;" :: "r"(sm), "l"(gp))
#define CP_COMMIT()      asm volatile("cp.async.commit_group;" ::: "memory")
#define CP_WAIT1()       asm volatile("cp.async.wait_group 1;" ::: "memory")
#define LDMX4(r0, r1, r2, r3, a) \
    asm volatile("ldmatrix.sync.aligned.m8n8.x4.shared.b16 {%0,%1,%2,%3}, [%4];" \
        : "=r"(r0), "=r"(r1), "=r"(r2), "=r"(r3) : "r"(a))
#define MMA16816(d, a0, a1, a2, a3, b0, b1) \
    asm volatile("mma.sync.aligned.m16n8k16.row.col.f32.bf16.bf16.f32 " \
        "{%0,%1,%2,%3}, {%4,%5,%6,%7}, {%8,%9}, {%0,%1,%2,%3};" \
        : "+f"((d)[0]), "+f"((d)[1]), "+f"((d)[2]), "+f"((d)[3]) \
        : "r"(a0), "r"(a1), "r"(a2), "r"(a3), "r"(b0), "r"(b1))

__device__ __forceinline__ void split2(float x, unsigned short& h, unsigned short& l) {
    __nv_bfloat16 hb = __float2bfloat16(x);
    h = __bfloat16_as_ushort(hb);
    l = __bfloat16_as_ushort(__float2bfloat16(x - __bfloat162float(hb)));
}
__device__ __forceinline__ unsigned pack2(float a, float b) {
    unsigned short ha, hb_;
    __nv_bfloat16 t = __float2bfloat16(a); ha = __bfloat16_as_ushort(t);
    t = __float2bfloat16(b); hb_ = __bfloat16_as_ushort(t);
    return (unsigned)ha | ((unsigned)hb_ << 16);
}

// ---------------- h = hidden + injection, fused hi/lo split ----------------
__global__ void add3_kernel(const float* __restrict__ a, const float* __restrict__ b,
                            unsigned short* __restrict__ hi, unsigned short* __restrict__ lo) {
    long i = (long)blockIdx.x * 256 + threadIdx.x;
    float4 va = ((const float4*)a)[i];
    float4 vb = ((const float4*)b)[i];
    float x[4] = {va.x + vb.x, va.y + vb.y, va.z + vb.z, va.w + vb.w};
    ((float4*)g_h)[i] = make_float4(x[0], x[1], x[2], x[3]);
    unsigned int h[4], l[4];
#pragma unroll
    for (int j = 0; j < 4; j++) { unsigned short hs_, ls_; split2(x[j], hs_, ls_); h[j] = hs_; l[j] = ls_; }
    uint2 uh, ul;
    uh.x = h[0] | (h[1] << 16); uh.y = h[2] | (h[3] << 16);
    ul.x = l[0] | (l[1] << 16); ul.y = l[2] | (l[3] << 16);
    ((uint2*)hi)[i] = uh; ((uint2*)lo)[i] = ul;
}

// ---------------- fp32 -> 2 bf16 planes (weights) ----------------
__global__ void cvt2_kernel(const float* __restrict__ src,
                            unsigned short* __restrict__ hi, unsigned short* __restrict__ lo) {
    long i = (long)blockIdx.x * 256 + threadIdx.x;
    float4 v = ((const float4*)src)[i];
    float x[4] = {v.x, v.y, v.z, v.w};
    unsigned int h[4], l[4];
#pragma unroll
    for (int j = 0; j < 4; j++) { unsigned short hs_, ls_; split2(x[j], hs_, ls_); h[j] = hs_; l[j] = ls_; }
    uint2 uh, ul;
    uh.x = h[0] | (h[1] << 16); uh.y = h[2] | (h[3] << 16);
    ul.x = l[0] | (l[1] << 16); ul.y = l[2] | (l[3] << 16);
    ((uint2*)hi)[i] = uh; ((uint2*)lo)[i] = ul;
}

// ---------------- routing ----------------
__global__ void routing_kernel(const float* __restrict__ gate_w, float* __restrict__ aux_out) {
    __shared__ float logits[Bb][Ee];
    __shared__ float probs[Bb][Ee];
    int tid = threadIdx.x;
    if (tid < Bb * Ee) {
        int b = tid >> 3, e = tid & 7;
        const float* hv = g_h + (long)b * Ss * Hh;
        const float* w = gate_w + e * Hh;
        float acc = 0.f;
        for (int i = 0; i < Hh; i++) acc += hv[i] * w[i];
        logits[b][e] = acc;
    }
    __syncthreads();
    if (tid < Bb) {
        int b = tid;
        float mx = -1e30f;
        for (int e = 0; e < Ee; e++) mx = fmaxf(mx, logits[b][e]);
        float p[Ee]; float sum = 0.f;
        for (int e = 0; e < Ee; e++) { p[e] = expf(logits[b][e] - mx); sum += p[e]; }
        for (int e = 0; e < Ee; e++) { p[e] /= sum; probs[b][e] = p[e]; }
        int i1 = 0;
        for (int e = 1; e < Ee; e++) if (p[e] > p[i1]) i1 = e;
        int i2 = -1; float v2 = -1e30f;
        for (int e = 0; e < Ee; e++) if (e != i1 && p[e] > v2) { v2 = p[e]; i2 = e; }
        float denom = fmaxf(p[i1] + v2, 1e-8f);
        g_pair_e[2 * b]     = i1; g_pair_w[2 * b]     = p[i1] / denom;
        g_pair_e[2 * b + 1] = i2; g_pair_w[2 * b + 1] = v2 / denom;
    }
    __syncthreads();
    if (tid == 0) {
        float aux = 0.f;
        for (int e = 0; e < Ee; e++) {
            float imp = 0.f;
            for (int b = 0; b < Bb; b++) imp += probs[b][e];
            imp /= (float)Bb;
            int cnt = 0;
            for (int p = 0; p < NPAIR; p++) if (g_pair_e[p] == e) cnt++;
            float loadf = (float)cnt / (float)(Bb * 2);
            aux += (float)Ee * imp * loadf;
        }
        *aux_out = aux;
    }
}

// ---------------- 4-tile mma GEMM: 3-term exact bf16, BK=32, 3-stage ----------------
// stage: Ahi | Alo | Whi | Wlo, each 128x32 bf16 (64B rows, SW64 swizzle) = 32KB
#define STG   32768
#define T_AL  8192
#define T_WH  16384
#define T_WL  24576

__global__ void __launch_bounds__(256, 2) gemm_mma(
    const unsigned short* __restrict__ Ah, const unsigned short* __restrict__ Al, int aDiv,
    const unsigned short* __restrict__ Wh, const unsigned short* __restrict__ Wl,
    float* __restrict__ C, int K, int N,
    unsigned short* __restrict__ Ph, unsigned short* __restrict__ Pl)
{
    extern __shared__ __align__(1024) char sm[];
    uint32_t sb = smem_u32(sm);

    int tid = threadIdx.x;
    int wid = tid >> 5, lane = tid & 31;
    int wm = wid & 1, wn = wid >> 1;
    int pair = blockIdx.z;
    int m0 = blockIdx.x * 128, n0 = blockIdx.y * 128;   // m innermost: W reused across 4 CTAs

    const unsigned short* pAh = Ah + (long)(pair / aDiv) * Ss * K + (long)m0 * K;
    const unsigned short* pAl = Al + (long)(pair / aDiv) * Ss * K + (long)m0 * K;
    const unsigned short* pWh = Wh + (long)g_pair_e[pair] * N * K + (long)n0 * K;
    const unsigned short* pWl = Wl + (long)g_pair_e[pair] * N * K + (long)n0 * K;

    // cp.async: thread t -> rows (t>>2)+64j, 16B chunk t&3; SW64 swizzle
    int r_ = tid >> 2, c_ = tid & 3;
    uint32_t so[2]; long go[2];
#pragma unroll
    for (int j = 0; j < 2; j++) {
        int row = r_ + 64 * j;
        so[j] = row * 64 + ((c_ ^ ((row >> 1) & 3)) << 4);
        go[j] = (long)row * K + c_ * 8;
    }

    // ldmatrix lane addressing (row stride 64B)
    int l8 = lane & 7;
    int rowA = l8 + 8 * ((lane >> 3) & 1);
    int cA = lane >> 4;
    int rowB = l8 + 8 * (lane >> 4);
    int cB = (lane >> 3) & 1;
    int swA = (rowA >> 1) & 3, swB = (rowB >> 1) & 3;
    uint32_t aOff = (uint32_t)(wm * 64 + rowA) * 64;
    uint32_t bOff = (uint32_t)(wn * 32 + rowB) * 64;

    float acc[4][4][4];
#pragma unroll
    for (int i = 0; i < 4; i++)
#pragma unroll
        for (int j = 0; j < 4; j++)
#pragma unroll
            for (int k = 0; k < 4; k++) acc[i][j][k] = 0.f;

    int nc = K >> 5;

#pragma unroll
    for (int s = 0; s < 2; s++) {
        uint32_t st = sb + s * STG;
        long kb = (long)s * 32;
#pragma unroll
        for (int j = 0; j < 2; j++) {
            CP_ASYNC(st + so[j],        pAh + go[j] + kb);
            CP_ASYNC(st + T_AL + so[j], pAl + go[j] + kb);
            CP_ASYNC(st + T_WH + so[j], pWh + go[j] + kb);
            CP_ASYNC(st + T_WL + so[j], pWl + go[j] + kb);
        }
        CP_COMMIT();
    }

    int sIdx = 0;
    for (int c = 0; c < nc; c++) {
        CP_WAIT1();
        __syncthreads();
        if (c + 2 < nc) {
            int s2 = sIdx + 2; if (s2 >= 3) s2 -= 3;
            uint32_t st = sb + s2 * STG;
            long kb = (long)(c + 2) * 32;
#pragma unroll
            for (int j = 0; j < 2; j++) {
                CP_ASYNC(st + so[j],        pAh + go[j] + kb);
                CP_ASYNC(st + T_AL + so[j], pAl + go[j] + kb);
                CP_ASYNC(st + T_WH + so[j], pWh + go[j] + kb);
                CP_ASYNC(st + T_WL + so[j], pWl + go[j] + kb);
            }
            CP_COMMIT();
        } else {
            CP_COMMIT();
        }

        uint32_t st = sb + sIdx * STG;
#pragma unroll
        for (int kk = 0; kk < 2; kk++) {
            uint32_t kxA = (uint32_t)(((2 * kk + cA) ^ swA) << 4);
            uint32_t kxB = (uint32_t)(((2 * kk + cB) ^ swB) << 4);
            unsigned af[4][4], bh[4][2], bl[4][2];
            // Ahi fragments
#pragma unroll
            for (int mt = 0; mt < 4; mt++)
                LDMX4(af[mt][0], af[mt][1], af[mt][2], af[mt][3], st + aOff + mt * 1024 + kxA);
            // Whi fragments
            LDMX4(bh[0][0], bh[0][1], bh[1][0], bh[1][1], st + T_WH + bOff + kxB);
            LDMX4(bh[2][0], bh[2][1], bh[3][0], bh[3][1], st + T_WH + bOff + 1024 + kxB);
#pragma unroll
            for (int mt = 0; mt < 4; mt++)
#pragma unroll
                for (int nt = 0; nt < 4; nt++)
                    MMA16816(acc[mt][nt], af[mt][0], af[mt][1], af[mt][2], af[mt][3], bh[nt][0], bh[nt][1]);
            // Wlo fragments, reuse Ahi
            LDMX4(bl[0][0], bl[0][1], bl[1][0], bl[1][1], st + T_WL + bOff + kxB);
            LDMX4(bl[2][0], bl[2][1], bl[3][0], bl[3][1], st + T_WL + bOff + 1024 + kxB);
#pragma unroll
            for (int mt = 0; mt < 4; mt++)
#pragma unroll
                for (int nt = 0; nt < 4; nt++)
                    MMA16816(acc[mt][nt], af[mt][0], af[mt][1], af[mt][2], af[mt][3], bl[nt][0], bl[nt][1]);
            // Alo fragments (reuse af registers), with Whi
#pragma unroll
            for (int mt = 0; mt < 4; mt++)
                LDMX4(af[mt][0], af[mt][1], af[mt][2], af[mt][3], st + T_AL + aOff + mt * 1024 + kxA);
#pragma unroll
            for (int mt = 0; mt < 4; mt++)
#pragma unroll
                for (int nt = 0; nt < 4; nt++)
                    MMA16816(acc[mt][nt], af[mt][0], af[mt][1], af[mt][2], af[mt][3], bh[nt][0], bh[nt][1]);
        }
        sIdx++; if (sIdx >= 3) sIdx -= 3;
    }

    int g = lane >> 2, t2 = (lane & 3) * 2;
    float* Cp = C + (long)pair * Ss * N;
#pragma unroll
    for (int mt = 0; mt < 4; mt++) {
        int m = m0 + wm * 64 + mt * 16 + g;
#pragma unroll
        for (int nt = 0; nt < 4; nt++) {
            int n = n0 + wn * 32 + nt * 8 + t2;
            *(float2*)(Cp + (long)m * N + n)       = make_float2(acc[mt][nt][0], acc[mt][nt][1]);
            *(float2*)(Cp + (long)(m + 8) * N + n) = make_float2(acc[mt][nt][2], acc[mt][nt][3]);
            if (Ph) {
                long r0 = ((long)pair * Ss + m) * N + n;
                long r1 = ((long)pair * Ss + m + 8) * N + n;
                unsigned short h0, l0, h1, l1;
                split2(acc[mt][nt][0], h0, l0); split2(acc[mt][nt][1], h1, l1);
                *(unsigned*)(Ph + r0) = (unsigned)h0 | ((unsigned)h1 << 16);
                *(unsigned*)(Pl + r0) = (unsigned)l0 | ((unsigned)l1 << 16);
                split2(acc[mt][nt][2], h0, l0); split2(acc[mt][nt][3], h1, l1);
                *(unsigned*)(Ph + r1) = (unsigned)h0 | ((unsigned)h1 << 16);
                *(unsigned*)(Pl + r1) = (unsigned)l0 | ((unsigned)l1 << 16);
            }
        }
    }
}

// ---------------- prep attention: rope + scale + hi/lo split + V transpose ----------------
__global__ void prep_attn(const float* __restrict__ cosb, const float* __restrict__ sinb) {
    int s = blockIdx.x, pair = blockIdx.y;
    int tid = threadIdx.x;
    int hh = tid >> 5, d = tid & 31;
    const float* base = g_qkv + ((long)pair * Ss + s) * QKVW;
    long ph = (long)pair * 8 + hh;
    float c1 = cosb[s * HD + d],      s1 = sinb[s * HD + d];
    float c2 = cosb[s * HD + d + 32], s2 = sinb[s * HD + d + 32];
    {
        float x1 = base[hh * HD + d], x2 = base[hh * HD + d + 32];
        float y1 = (x1 * c1 - x2 * s1) * 0.125f;
        float y2 = (x2 * c2 + x1 * s2) * 0.125f;
        long o = (ph * Ss + s) * HD + d;
        unsigned short h0, l0, h1, l1;
        split2(y1, h0, l0); split2(y2, h1, l1);
        g_aw[WQH + o] = h0; g_aw[WQL + o] = l0;
        g_aw[WQH + o + 32] = h1; g_aw[WQL + o + 32] = l1;
    }
    {
        float x1 = base[512 + hh * HD + d], x2 = base[512 + hh * HD + d + 32];
        float y1 = x1 * c1 - x2 * s1;
        float y2 = x2 * c2 + x1 * s2;
        long o = (ph * Ss + s) * HD + d;
        unsigned short h0, l0, h1, l1;
        split2(y1, h0, l0); split2(y2, h1, l1);
        g_aw[WKH + o] = h0; g_aw[WKL + o] = l0;
        g_aw[WKH + o + 32] = h1; g_aw[WKL + o + 32] = l1;
    }
    {
        float v1 = base[1024 + hh * HD + d], v2 = base[1024 + hh * HD + d + 32];
        long o1 = (ph * HD + d) * Ss + s;
        long o2 = (ph * HD + d + 32) * Ss + s;
        unsigned short h0, l0, h1, l1;
        split2(v1, h0, l0); split2(v2, h1, l1);
        g_aw[WVH + o1] = h0; g_aw[WVL + o1] = l0;
        g_aw[WVH + o2] = h1; g_aw[WVL + o2] = l1;
    }
}

// ---------------- mma flash attention, epilogue writes hi/lo planes ----------------
#define ASMEM 98304

__global__ void __launch_bounds__(256) attn_mma(unsigned short* __restrict__ Ph,
                                                unsigned short* __restrict__ Pl) {
    extern __shared__ __align__(1024) char sm2[];
    uint32_t sb = smem_u32(sm2);
    int tid = threadIdx.x, w = tid >> 5, lane = tid & 31;
    int qt = blockIdx.x, head = blockIdx.y, pair = blockIdx.z;
    int q0 = qt * 128;
    long ph = (long)pair * 8 + head;
    const unsigned short* Qh = g_aw + WQH + ph * Ss * HD;
    const unsigned short* Ql = g_aw + WQL + ph * Ss * HD;
    const unsigned short* Kh = g_aw + WKH + ph * Ss * HD;
    const unsigned short* Kl = g_aw + WKL + ph * Ss * HD;
    const unsigned short* Vh = g_aw + WVH + ph * HD * Ss;
    const unsigned short* Vl = g_aw + WVL + ph * HD * Ss;

    int ldRow = tid >> 3, ldC = tid & 7;

#pragma unroll
    for (int j = 0; j < 4; j++) {
        int row = ldRow + 32 * j;
        uint32_t so = row * 128 + ((ldC ^ (row & 7)) << 4);
        CP_ASYNC(sb + so,         Qh + (long)(q0 + row) * HD + ldC * 8);
        CP_ASYNC(sb + 16384 + so, Ql + (long)(q0 + row) * HD + ldC * 8);
    }
    auto issue = [&](int buf, int kt) {
        uint32_t st = sb + 32768 + buf * 32768;
#pragma unroll
        for (int j = 0; j < 2; j++) {
            int row = ldRow + 32 * j;
            uint32_t so = row * 128 + ((ldC ^ (row & 7)) << 4);
            long kOff = (long)(kt * 64 + row) * HD + ldC * 8;
            CP_ASYNC(st + so,         Kh + kOff);
            CP_ASYNC(st + 8192 + so,  Kl + kOff);
            long vOff = (long)row * Ss + kt * 64 + ldC * 8;
            CP_ASYNC(st + 16384 + so, Vh + vOff);
            CP_ASYNC(st + 24576 + so, Vl + vOff);
        }
    };
    issue(0, 0); CP_COMMIT();
    issue(1, 1); CP_COMMIT();

    int l8 = lane & 7;
    int rowA = l8 + 8 * ((lane >> 3) & 1);
    int cA = lane >> 4;
    int rowB = l8 + 8 * (lane >> 4);
    int cB = (lane >> 3) & 1;
    uint32_t aOff = (uint32_t)(w * 16 + rowA) * 128;
    uint32_t bOff = (uint32_t)rowB * 128;

    float o[8][4];
#pragma unroll
    for (int f = 0; f < 8; f++)
#pragma unroll
        for (int k = 0; k < 4; k++) o[f][k] = 0.f;
    float mr[2] = {-1e30f, -1e30f}, lr[2] = {0.f, 0.f};

    for (int kt = 0; kt < 8; kt++) {
        CP_WAIT1();
        __syncthreads();
        int buf = kt & 1;
        uint32_t st = sb + 32768 + buf * 32768;

        float sc[8][4];
#pragma unroll
        for (int f = 0; f < 8; f++)
#pragma unroll
            for (int k = 0; k < 4; k++) sc[f][k] = 0.f;
#pragma unroll
        for (int pass = 0; pass < 3; pass++) {
            uint32_t aB = sb + (pass == 1 ? 16384u : 0u) + aOff;
            uint32_t bB = st + (pass == 2 ? 8192u : 0u) + bOff;
#pragma unroll
            for (int kk = 0; kk < 4; kk++) {
                unsigned af[4], bfr[8][2];
                uint32_t kxA = (uint32_t)(((2 * kk + cA) ^ l8) << 4);
                uint32_t kxB = (uint32_t)(((2 * kk + cB) ^ l8) << 4);
                LDMX4(af[0], af[1], af[2], af[3], aB + kxA);
#pragma unroll
                for (int n2 = 0; n2 < 4; n2++)
                    LDMX4(bfr[2*n2][0], bfr[2*n2][1], bfr[2*n2+1][0], bfr[2*n2+1][1],
                          bB + n2 * 2048 + kxB);
#pragma unroll
                for (int nt = 0; nt < 8; nt++)
                    MMA16816(sc[nt], af[0], af[1], af[2], af[3], bfr[nt][0], bfr[nt][1]);
            }
        }

#pragma unroll
        for (int r = 0; r < 2; r++) {
            float mx = -1e30f;
#pragma unroll
            for (int f = 0; f < 8; f++) mx = fmaxf(mx, fmaxf(sc[f][2*r], sc[f][2*r+1]));
            mx = fmaxf(mx, __shfl_xor_sync(0xffffffffu, mx, 1));
            mx = fmaxf(mx, __shfl_xor_sync(0xffffffffu, mx, 2));
            float mn = fmaxf(mr[r], mx);
            float scale = expf(mr[r] - mn);
            mr[r] = mn;
            float ls = 0.f;
#pragma unroll
            for (int f = 0; f < 8; f++) {
                float p0 = expf(sc[f][2*r] - mn);
                float p1 = expf(sc[f][2*r+1] - mn);
                sc[f][2*r] = p0; sc[f][2*r+1] = p1;
                ls += p0 + p1;
            }
            ls += __shfl_xor_sync(0xffffffffu, ls, 1);
            ls += __shfl_xor_sync(0xffffffffu, ls, 2);
            lr[r] = lr[r] * scale + ls;
#pragma unroll
            for (int f = 0; f < 8; f++) { o[f][2*r] *= scale; o[f][2*r+1] *= scale; }
        }

        unsigned aPh[4][4], aPl[4][4];
#pragma unroll
        for (int j = 0; j < 4; j++) {
#pragma unroll
            for (int u = 0; u < 4; u++) {
                int f = 2 * j + (u >> 1);
                int c = (u & 1) * 2;
                unsigned short h0, l0, h1, l1;
                split2(sc[f][c], h0, l0);
                split2(sc[f][c + 1], h1, l1);
                aPh[j][u] = (unsigned)h0 | ((unsigned)h1 << 16);
                aPl[j][u] = (unsigned)l0 | ((unsigned)l1 << 16);
            }
        }

#pragma unroll
        for (int pass = 0; pass < 3; pass++) {
            uint32_t vB = st + (pass == 2 ? 24576u : 16384u) + bOff;
#pragma unroll
            for (int j = 0; j < 4; j++) {
                unsigned bfr[8][2];
                uint32_t kxB = (uint32_t)(((2 * j + cB) ^ l8) << 4);
#pragma unroll
                for (int n2 = 0; n2 < 4; n2++)
                    LDMX4(bfr[2*n2][0], bfr[2*n2][1], bfr[2*n2+1][0], bfr[2*n2+1][1],
                          vB + n2 * 2048 + kxB);
                const unsigned (*aP)[4] = (pass == 1) ? aPl : aPh;
#pragma unroll
                for (int nt = 0; nt < 8; nt++)
                    MMA16816(o[nt], aP[j][0], aP[j][1], aP[j][2], aP[j][3],
                             bfr[nt][0], bfr[nt][1]);
            }
        }
        __syncthreads();
        if (kt + 2 < 8) issue(buf, kt + 2);
        CP_COMMIT();
    }

    int g = lane >> 2, t2 = (lane & 3) * 2;
#pragma unroll
    for (int r = 0; r < 2; r++) {
        float inv = 1.f / lr[r];
        long row = (long)pair * Ss + q0 + w * 16 + g + 8 * r;
#pragma unroll
        for (int nt = 0; nt < 8; nt++) {
            float y0 = o[nt][2*r] * inv, y1 = o[nt][2*r+1] * inv;
            unsigned short h0, l0, h1, l1;
            split2(y0, h0, l0); split2(y1, h1, l1);
            long off = row * HSUB + head * HD + nt * 8 + t2;
            *(unsigned*)(Ph + off) = (unsigned)h0 | ((unsigned)h1 << 16);
            *(unsigned*)(Pl + off) = (unsigned)l0 | ((unsigned)l1 << 16);
        }
    }
}

// ---------------- residual + rmsnorm, fused hi/lo split ----------------
__global__ void resnorm2_kernel(unsigned short* __restrict__ Ph, unsigned short* __restrict__ Pl) {
    long row = blockIdx.x;
    float* a = g_hs + row * HSUB;
    const float* t = g_tmp + row * HSUB;
    int tid = threadIdx.x;
    float v0 = a[tid] + t[tid];
    float v1 = a[tid + 256] + t[tid + 256];
    float ss = v0 * v0 + v1 * v1;
#pragma unroll
    for (int off = 16; off; off >>= 1) ss += __shfl_xor_sync(0xffffffffu, ss, off);
    __shared__ float red[8];
    __shared__ float stot;
    if ((tid & 31) == 0) red[tid >> 5] = ss;
    __syncthreads();
    if (tid == 0) {
        float tsum = 0.f;
        for (int i = 0; i < 8; i++) tsum += red[i];
        stot = tsum;
    }
    __syncthreads();
    float scale = rsqrtf(stot * (1.f / HSUB) + 1e-5f);
    float y0 = v0 * scale, y1 = v1 * scale;
    a[tid] = y0; a[tid + 256] = y1;
    unsigned short h, l;
    split2(y0, h, l); Ph[row * HSUB + tid] = h; Pl[row * HSUB + tid] = l;
    split2(y1, h, l); Ph[row * HSUB + tid + 256] = h; Pl[row * HSUB + tid + 256] = l;
}

// ---------------- silu(gate)*up fused split ----------------
__global__ void silu2_kernel(unsigned short* __restrict__ Ph, unsigned short* __restrict__ Pl) {
    long i = (long)blockIdx.x * 256 + threadIdx.x;
    long row = i / (INTER / 4);
    int c4 = (int)(i - row * (INTER / 4));
    const float* gr = g_gu + row * GUW;
    float4 gv = *(const float4*)(gr + c4 * 4);
    float4 uv = *(const float4*)(gr + INTER + c4 * 4);
    float x[4];
    x[0] = gv.x / (1.f + expf(-gv.x)) * uv.x;
    x[1] = gv.y / (1.f + expf(-gv.y)) * uv.y;
    x[2] = gv.z / (1.f + expf(-gv.z)) * uv.z;
    x[3] = gv.w / (1.f + expf(-gv.w)) * uv.w;
    unsigned int h[4], l[4];
#pragma unroll
    for (int j = 0; j < 4; j++) { unsigned short hs_, ls_; split2(x[j], hs_, ls_); h[j] = hs_; l[j] = ls_; }
    uint2 uh, ul;
    uh.x = h[0] | (h[1] << 16); uh.y = h[2] | (h[3] << 16);
    ul.x = l[0] | (l[1] << 16); ul.y = l[2] | (l[3] << 16);
    long base = row * INTER + (long)c4 * 4;
    *(uint2*)(Ph + base) = uh;
    *(uint2*)(Pl + base) = ul;
}

// ---------------- final ----------------
__global__ void final_kernel(float* __restrict__ out) {
    int b = blockIdx.y, s = blockIdx.x;
    float w0 = g_pair_w[2 * b], w1 = g_pair_w[2 * b + 1];
    long r = (long)b * Ss + s;
    const float* hp = g_h + r * Hh;
    const float* u0 = g_up + ((long)(2 * b) * Ss + s) * Hh;
    const float* u1 = g_up + ((long)(2 * b + 1) * Ss + s) * Hh;
    int tid = threadIdx.x;
    int c = tid * 4;
    float4 vh = *(const float4*)(hp + c);
    float4 v0 = *(const float4*)(u0 + c);
    float4 v1 = *(const float4*)(u1 + c);
    float y[4];
    y[0] = vh.x + w0 * v0.x + w1 * v1.x;
    y[1] = vh.y + w0 * v0.y + w1 * v1.y;
    y[2] = vh.z + w0 * v0.z + w1 * v1.z;
    y[3] = vh.w + w0 * v0.w + w1 * v1.w;
    float ss = y[0] * y[0] + y[1] * y[1] + y[2] * y[2] + y[3] * y[3];
#pragma unroll
    for (int off = 16; off; off >>= 1) ss += __shfl_xor_sync(0xffffffffu, ss, off);
    __shared__ float red[8];
    __shared__ float stot;
    if ((tid & 31) == 0) red[tid >> 5] = ss;
    __syncthreads();
    if (tid == 0) {
        float tsum = 0.f;
        for (int i = 0; i < 8; i++) tsum += red[i];
        stot = tsum;
    }
    __syncthreads();
    float scale = rsqrtf(stot * (1.f / Hh) + 1e-5f);
    float4 o;
    o.x = y[0] * scale; o.y = y[1] * scale; o.z = y[2] * scale; o.w = y[3] * scale;
    *(float4*)(out + r * Hh + c) = o;
}

// ---------------- launch ----------------
extern "C" void kernel_launch(void* const* d_in, const int* in_sizes, int n_in,
                              void* d_out, int out_size) {
    const float* hidden     = (const float*)d_in[0];
    const float* inj        = (const float*)d_in[1];
    const float* cosb       = (const float*)d_in[2];
    const float* sinb       = (const float*)d_in[3];
    const float* gate_w     = (const float*)d_in[4];
    const float* down_w     = (const float*)d_in[5];
    const float* up_w       = (const float*)d_in[6];
    const float* qkv_w      = (const float*)d_in[7];
    const float* o_w        = (const float*)d_in[8];
    const float* gate_up_w  = (const float*)d_in[9];
    const float* mlp_down_w = (const float*)d_in[10];
    float* out = (float*)d_out;

    void* vp;
    cudaGetSymbolAddress(&vp, g_hs);  float* p_hs  = (float*)vp;
    cudaGetSymbolAddress(&vp, g_qkv); float* p_qkv = (float*)vp;
    cudaGetSymbolAddress(&vp, g_tmp); float* p_tmp = (float*)vp;
    cudaGetSymbolAddress(&vp, g_gu);  float* p_gu  = (float*)vp;
    cudaGetSymbolAddress(&vp, g_up);  float* p_up  = (float*)vp;
    cudaGetSymbolAddress(&vp, g_wh);  unsigned short* p_wh = (unsigned short*)vp;
    cudaGetSymbolAddress(&vp, g_wl);  unsigned short* p_wl = (unsigned short*)vp;
    cudaGetSymbolAddress(&vp, g_p0h); unsigned short* p0h = (unsigned short*)vp;
    cudaGetSymbolAddress(&vp, g_p0l); unsigned short* p0l = (unsigned short*)vp;
    cudaGetSymbolAddress(&vp, g_p1h); unsigned short* p1h = (unsigned short*)vp;
    cudaGetSymbolAddress(&vp, g_p1l); unsigned short* p1l = (unsigned short*)vp;

    cudaFuncSetAttribute(gemm_mma, cudaFuncAttributeMaxDynamicSharedMemorySize, 3 * STG);
    cudaFuncSetAttribute(attn_mma, cudaFuncAttributeMaxDynamicSharedMemorySize, ASMEM);

    // weight 2-plane conversion
    cvt2_kernel<<<(int)(4194304L / 4 / 256), 256>>>(down_w,     p_wh + OFF_DOWN, p_wl + OFF_DOWN);
    cvt2_kernel<<<(int)(6291456L / 4 / 256), 256>>>(qkv_w,      p_wh + OFF_QKV,  p_wl + OFF_QKV);
    cvt2_kernel<<<(int)(2097152L / 4 / 256), 256>>>(o_w,        p_wh + OFF_O,    p_wl + OFF_O);
    cvt2_kernel<<<(int)(12582912L / 4 / 256), 256>>>(gate_up_w, p_wh + OFF_GU,   p_wl + OFF_GU);
    cvt2_kernel<<<(int)(6291456L / 4 / 256), 256>>>(mlp_down_w, p_wh + OFF_MLPD, p_wl + OFF_MLPD);
    cvt2_kernel<<<(int)(4194304L / 4 / 256), 256>>>(up_w,       p_wh + OFF_UP,   p_wl + OFF_UP);

    // 1. h = hidden + injection (fused split into P0) ; routing
    add3_kernel<<<(Bb * Ss * Hh / 4) / 256, 256>>>(hidden, inj, p0h, p0l);
    routing_kernel<<<1, 64>>>(gate_w, out + (out_size - 1));

    // 2. hs0 = h @ down_w^T  (K=1024) ; epilogue writes planes -> P1
    gemm_mma<<<dim3(4, HSUB / 128, NPAIR), 256, 3 * STG>>>(
        p0h, p0l, 2, p_wh + OFF_DOWN, p_wl + OFF_DOWN, p_hs, Hh, HSUB, p1h, p1l);

    // 3. qkv = hs0 @ qkv_w^T  (K=512)
    gemm_mma<<<dim3(4, QKVW / 128, NPAIR), 256, 3 * STG>>>(
        p1h, p1l, 1, p_wh + OFF_QKV, p_wl + OFF_QKV, p_qkv, HSUB, QKVW, (unsigned short*)0, (unsigned short*)0);

    // 4. prep + attention (writes planes -> P0)
    prep_attn<<<dim3(Ss, NPAIR), 256>>>(cosb, sinb);
    attn_mma<<<dim3(4, NHEAD, NPAIR), 256, ASMEM>>>(p0h, p0l);

    // 5. tmp = att @ o_w^T  (K=512)
    gemm_mma<<<dim3(4, HSUB / 128, NPAIR), 256, 3 * STG>>>(
        p0h, p0l, 1, p_wh + OFF_O, p_wl + OFF_O, p_tmp, HSUB, HSUB, (unsigned short*)0, (unsigned short*)0);

    // 6. hs1 = rmsnorm(hs0 + tmp) -> planes P1
    resnorm2_kernel<<<NPAIR * Ss, 256>>>(p1h, p1l);

    // 7. gu = hs1 @ gate_up_w^T  (K=512)
    gemm_mma<<<dim3(4, GUW / 128, NPAIR), 256, 3 * STG>>>(
        p1h, p1l, 1, p_wh + OFF_GU, p_wl + OFF_GU, p_gu, HSUB, GUW, (unsigned short*)0, (unsigned short*)0);

    // 8. act = silu(gate)*up -> planes P0
    silu2_kernel<<<(NPAIR * Ss * INTER / 4) / 256, 256>>>(p0h, p0l);

    // 9. tmp = act @ mlp_down_w^T  (K=1536)
    gemm_mma<<<dim3(4, HSUB / 128, NPAIR), 256, 3 * STG>>>(
        p0h, p0l, 1, p_wh + OFF_MLPD, p_wl + OFF_MLPD, p_tmp, INTER, HSUB, (unsigned short*)0, (unsigned short*)0);

    // 10. hs2 = rmsnorm(hs1 + tmp) -> planes P1
    resnorm2_kernel<<<NPAIR * Ss, 256>>>(p1h, p1l);

    // 11. up_out = hs2 @ up_w^T  (K=512)
    gemm_mma<<<dim3(4, Hh / 128, NPAIR), 256, 3 * STG>>>(
        p1h, p1l, 1, p_wh + OFF_UP, p_wl + OFF_UP, p_up, HSUB, Hh, (unsigned short*)0, (unsigned short*)0);

    // 12. out = rmsnorm(h + w0*u0 + w1*u1)
    final_kernel<<<dim3(Ss, Bb), 256>>>(out);
}